// round 1
// baseline (speedup 1.0000x reference)
#include <cuda_runtime.h>
#include <math.h>

#define N_ROWS 500000
#define TPB 512

// ---------------- shared-memory layout (floats) ----------------
// padded so all vectorized LDS are 8B/16B aligned
#define OFF_W1   0          // 100 x 200
#define OFF_B1   20000      // 100
#define OFF_W12  20100      // 50 x 100
#define OFF_B12  25100      // 50
#define OFF_W13  25152      // 30 x 152  (cols: [0..49]=z2 part, [52..151]=h part)
#define OFF_B13  29712      // 30
#define OFF_W14  29744      // 20 x 32
#define OFF_B14  30384      // 20
#define OFF_W15  30408      // 40 x 120
#define OFF_B15  35208      // 40
#define OFF_W2   35248      // 100 x 40
#define OFF_B2   39248      // 100
#define SH_FLOATS 39348
#define SH_BYTES (SH_FLOATS * 4)

#define OUT_SCALAR ((size_t)N_ROWS * 100)

// ---------------- global accumulators ----------------
__device__ double g_p0;
__device__ double g_sq;
__device__ double g_diff;
__device__ double g_mu[100];

__global__ void init_kernel() {
    int t = threadIdx.x;
    if (t == 0) { g_p0 = 0.0; g_sq = 0.0; g_diff = 0.0; }
    if (t < 100) g_mu[t] = 0.0;
}

// ---------------- fused MLP, thread-per-row ----------------
__global__ void __launch_bounds__(TPB, 1) fused_mlp(
    const float* __restrict__ x, const float* __restrict__ h,
    const float* __restrict__ w1,  const float* __restrict__ b1,
    const float* __restrict__ w12, const float* __restrict__ b12,
    const float* __restrict__ w13, const float* __restrict__ b13,
    const float* __restrict__ w14, const float* __restrict__ b14,
    const float* __restrict__ w15, const float* __restrict__ b15,
    const float* __restrict__ w2,  const float* __restrict__ b2,
    float* __restrict__ out)
{
    extern __shared__ float s[];
    const int tid = threadIdx.x;

    // cooperative weight staging
    for (int i = tid; i < 20000; i += TPB) s[OFF_W1 + i] = w1[i];
    for (int i = tid; i < 100;   i += TPB) s[OFF_B1 + i] = b1[i];
    for (int i = tid; i < 5000;  i += TPB) s[OFF_W12 + i] = w12[i];
    for (int i = tid; i < 50;    i += TPB) s[OFF_B12 + i] = b12[i];
    for (int i = tid; i < 4500;  i += TPB) {
        int r_ = i / 150, c = i % 150;
        s[OFF_W13 + r_ * 152 + (c < 50 ? c : c + 2)] = w13[i];
    }
    for (int i = tid; i < 30;    i += TPB) s[OFF_B13 + i] = b13[i];
    for (int i = tid; i < 600;   i += TPB) {
        int r_ = i / 30, c = i % 30;
        s[OFF_W14 + r_ * 32 + c] = w14[i];
    }
    for (int i = tid; i < 20;    i += TPB) s[OFF_B14 + i] = b14[i];
    for (int i = tid; i < 4800;  i += TPB) s[OFF_W15 + i] = w15[i];
    for (int i = tid; i < 40;    i += TPB) s[OFF_B15 + i] = b15[i];
    for (int i = tid; i < 4000;  i += TPB) s[OFF_W2 + i] = w2[i];
    for (int i = tid; i < 100;   i += TPB) s[OFF_B2 + i] = b2[i];
    __syncthreads();

    const int row = blockIdx.x * TPB + tid;
    float p0 = 0.0f;

    if (row < N_ROWS) {
        const float* xr = x + (size_t)row * 100;
        const float* hr = h + (size_t)row * 100;

        // ---- layer 1 (in two halves of 50 outputs) fused with layer 2 accumulation ----
        float z2[50];
        #pragma unroll
        for (int m = 0; m < 50; m++) z2[m] = s[OFF_B12 + m];

        #pragma unroll 1
        for (int half = 0; half < 2; ++half) {
            const float* wbase = s + OFF_W1 + half * 50 * 200;
            float a[50];
            #pragma unroll
            for (int j = 0; j < 50; j++) a[j] = s[OFF_B1 + half * 50 + j];

            // x contribution (k = 0..99)
            #pragma unroll 1
            for (int k = 0; k < 100; k += 4) {
                float4 in4 = *(const float4*)(xr + k);
                #pragma unroll
                for (int j = 0; j < 50; j++) {
                    float4 w = *(const float4*)(wbase + j * 200 + k);
                    a[j] = fmaf(w.x, in4.x, a[j]);
                    a[j] = fmaf(w.y, in4.y, a[j]);
                    a[j] = fmaf(w.z, in4.z, a[j]);
                    a[j] = fmaf(w.w, in4.w, a[j]);
                }
            }
            // h contribution (k = 100..199)
            #pragma unroll 1
            for (int k = 0; k < 100; k += 4) {
                float4 in4 = *(const float4*)(hr + k);
                #pragma unroll
                for (int j = 0; j < 50; j++) {
                    float4 w = *(const float4*)(wbase + j * 200 + 100 + k);
                    a[j] = fmaf(w.x, in4.x, a[j]);
                    a[j] = fmaf(w.y, in4.y, a[j]);
                    a[j] = fmaf(w.z, in4.z, a[j]);
                    a[j] = fmaf(w.w, in4.w, a[j]);
                }
            }
            #pragma unroll
            for (int j = 0; j < 50; j++) a[j] = fmaxf(a[j], 0.0f);

            // z2 += W12[:, half*50 : half*50+50] @ a
            const float* w12b = s + OFF_W12 + half * 50;
            #pragma unroll
            for (int m = 0; m < 50; m++) {
                float acc = z2[m];
                #pragma unroll
                for (int j = 0; j < 50; j += 2) {
                    float2 w = *(const float2*)(w12b + m * 100 + j);
                    acc = fmaf(w.x, a[j],     acc);
                    acc = fmaf(w.y, a[j + 1], acc);
                }
                z2[m] = acc;
            }
        }
        #pragma unroll
        for (int m = 0; m < 50; m++) z2[m] = fmaxf(z2[m], 0.0f);

        // ---- layer 3: z3 = relu(W13 @ [z2; h] + b13) ----
        float z3[30];
        #pragma unroll
        for (int m = 0; m < 30; m++) {
            float acc = s[OFF_B13 + m];
            const float* wrow = s + OFF_W13 + m * 152;
            #pragma unroll
            for (int j = 0; j < 50; j += 2) {
                float2 w = *(const float2*)(wrow + j);
                acc = fmaf(w.x, z2[j],     acc);
                acc = fmaf(w.y, z2[j + 1], acc);
            }
            z3[m] = acc;
        }
        #pragma unroll 1
        for (int k = 0; k < 100; k += 4) {
            float4 in4 = *(const float4*)(hr + k);
            #pragma unroll
            for (int m = 0; m < 30; m++) {
                float4 w = *(const float4*)(s + OFF_W13 + m * 152 + 52 + k);
                z3[m] = fmaf(w.x, in4.x, z3[m]);
                z3[m] = fmaf(w.y, in4.y, z3[m]);
                z3[m] = fmaf(w.z, in4.z, z3[m]);
                z3[m] = fmaf(w.w, in4.w, z3[m]);
            }
        }
        #pragma unroll
        for (int m = 0; m < 30; m++) z3[m] = fmaxf(z3[m], 0.0f);

        // ---- layer 4: z4 = relu(W14 @ z3 + b14) ----
        float z4[20];
        #pragma unroll
        for (int m = 0; m < 20; m++) {
            float acc = s[OFF_B14 + m];
            const float* wrow = s + OFF_W14 + m * 32;
            #pragma unroll
            for (int j = 0; j < 30; j += 2) {
                float2 w = *(const float2*)(wrow + j);
                acc = fmaf(w.x, z3[j],     acc);
                acc = fmaf(w.y, z3[j + 1], acc);
            }
            z4[m] = fmaxf(acc, 0.0f);
        }

        // ---- layer 5: z5 = relu(W15 @ [z4; h] + b15) ----
        float z5[40];
        #pragma unroll
        for (int m = 0; m < 40; m++) {
            float acc = s[OFF_B15 + m];
            const float* wrow = s + OFF_W15 + m * 120;
            #pragma unroll
            for (int j = 0; j < 20; j += 4) {
                float4 w = *(const float4*)(wrow + j);
                acc = fmaf(w.x, z4[j],     acc);
                acc = fmaf(w.y, z4[j + 1], acc);
                acc = fmaf(w.z, z4[j + 2], acc);
                acc = fmaf(w.w, z4[j + 3], acc);
            }
            z5[m] = acc;
        }
        #pragma unroll 1
        for (int k = 0; k < 100; k += 4) {
            float4 in4 = *(const float4*)(hr + k);
            #pragma unroll
            for (int m = 0; m < 40; m++) {
                float4 w = *(const float4*)(s + OFF_W15 + m * 120 + 20 + k);
                z5[m] = fmaf(w.x, in4.x, z5[m]);
                z5[m] = fmaf(w.y, in4.y, z5[m]);
                z5[m] = fmaf(w.z, in4.z, z5[m]);
                z5[m] = fmaf(w.w, in4.w, z5[m]);
            }
        }
        #pragma unroll
        for (int m = 0; m < 40; m++) z5[m] = fmaxf(z5[m], 0.0f);

        // ---- output layer: f = W2 @ z5 + b2, in 5 chunks of 20; fused part0 ----
        float* outr = out + (size_t)row * 100;
        const float* xn = x + (size_t)(row + 1) * 100;
        const bool hasnext = (row + 1 < N_ROWS);

        #pragma unroll 1
        for (int c = 0; c < 5; c++) {
            float facc[20];
            #pragma unroll
            for (int m = 0; m < 20; m++) {
                int mm = c * 20 + m;
                float acc = s[OFF_B2 + mm];
                const float* wrow = s + OFF_W2 + mm * 40;
                #pragma unroll
                for (int j = 0; j < 40; j += 4) {
                    float4 w = *(const float4*)(wrow + j);
                    acc = fmaf(w.x, z5[j],     acc);
                    acc = fmaf(w.y, z5[j + 1], acc);
                    acc = fmaf(w.z, z5[j + 2], acc);
                    acc = fmaf(w.w, z5[j + 3], acc);
                }
                facc[m] = acc;
            }
            #pragma unroll
            for (int m = 0; m < 20; m += 4) {
                float4 v = make_float4(facc[m], facc[m + 1], facc[m + 2], facc[m + 3]);
                *(float4*)(outr + c * 20 + m) = v;
                if (hasnext) {
                    float4 xv = *(const float4*)(xn + c * 20 + m);
                    float d0 = v.x - xv.x, d1 = v.y - xv.y;
                    float d2 = v.z - xv.z, d3 = v.w - xv.w;
                    p0 += d0 * d0 + d1 * d1 + d2 * d2 + d3 * d3;
                }
            }
        }
    }

    // ---- block reduction of part0 partial, one double atomic per CTA ----
    #pragma unroll
    for (int o = 16; o > 0; o >>= 1) p0 += __shfl_down_sync(0xffffffffu, p0, o);
    __shared__ float red[TPB / 32];
    const int wid = tid >> 5, lane = tid & 31;
    if (lane == 0) red[wid] = p0;
    __syncthreads();
    if (tid == 0) {
        float acc = 0.0f;
        #pragma unroll
        for (int i = 0; i < TPB / 32; i++) acc += red[i];
        atomicAdd(&g_p0, (double)acc);
    }
}

// ---------------- h statistics: mu (per-column mean), S, adjacent-row L1 ----
#define HS_ROWS 4096
__global__ void h_stats(const float* __restrict__ h) {
    const int col = threadIdx.x;  // 128 threads, cols 0..99 active
    const long long r0 = (long long)blockIdx.x * HS_ROWS;
    long long r1 = r0 + HS_ROWS; if (r1 > N_ROWS) r1 = N_ROWS;

    double csum = 0.0, sq = 0.0, dif = 0.0;
    if (col < 100 && r0 < N_ROWS) {
        float prev = h[r0 * 100 + col];
        csum += (double)prev; sq += (double)prev * (double)prev;
        for (long long r = r0 + 1; r < r1; ++r) {
            float v = h[r * 100 + col];
            csum += (double)v;
            sq   += (double)v * (double)v;
            dif  += (double)fabsf(v - prev);
            prev = v;
        }
        if (r1 < N_ROWS) {   // bridge pair (r1-1, r1)
            float v = h[r1 * 100 + col];
            dif += (double)fabsf(v - prev);
        }
        atomicAdd(&g_mu[col], csum);
    }

    // reduce sq/dif across block (shuffle doubles via two 32-bit halves is
    // avoided: use shared memory)
    __shared__ double ssq[128], sdf[128];
    ssq[threadIdx.x] = sq; sdf[threadIdx.x] = dif;
    __syncthreads();
    for (int off = 64; off > 0; off >>= 1) {
        if (threadIdx.x < off) {
            ssq[threadIdx.x] += ssq[threadIdx.x + off];
            sdf[threadIdx.x] += sdf[threadIdx.x + off];
        }
        __syncthreads();
    }
    if (threadIdx.x == 0) {
        atomicAdd(&g_sq,   ssq[0]);
        atomicAdd(&g_diff, sdf[0]);
    }
}

// ---------------- finalize scalars ----------------
__global__ void finalize(float* __restrict__ out) {
    if (threadIdx.x == 0 && blockIdx.x == 0) {
        double mu = 0.0;
        for (int j = 0; j < 100; j++) mu += fabs(g_mu[j] / (double)N_ROWS);
        out[OUT_SCALAR + 0] = (float)(sqrt(g_p0) / (double)(N_ROWS - 1));
        out[OUT_SCALAR + 1] = (float)(mu / 100.0);
        out[OUT_SCALAR + 2] = (float)fabs(g_sq / (double)N_ROWS / 100.0 - 1.0);
        out[OUT_SCALAR + 3] = (float)(g_diff / (double)(N_ROWS - 1) / 100.0);
    }
}

// ---------------- launch ----------------
extern "C" void kernel_launch(void* const* d_in, const int* in_sizes, int n_in,
                              void* d_out, int out_size) {
    const float* x   = (const float*)d_in[0];
    const float* h   = (const float*)d_in[1];
    const float* w1  = (const float*)d_in[2];
    const float* b1  = (const float*)d_in[3];
    const float* w12 = (const float*)d_in[4];
    const float* b12 = (const float*)d_in[5];
    const float* w13 = (const float*)d_in[6];
    const float* b13 = (const float*)d_in[7];
    const float* w14 = (const float*)d_in[8];
    const float* b14 = (const float*)d_in[9];
    const float* w15 = (const float*)d_in[10];
    const float* b15 = (const float*)d_in[11];
    const float* w2  = (const float*)d_in[12];
    const float* b2  = (const float*)d_in[13];
    float* out = (float*)d_out;

    (void)in_sizes; (void)n_in; (void)out_size;

    // >48KB dynamic shared; idempotent, capture-legal (not a stream op)
    cudaFuncSetAttribute(fused_mlp, cudaFuncAttributeMaxDynamicSharedMemorySize, SH_BYTES);

    init_kernel<<<1, 128>>>();
    fused_mlp<<<(N_ROWS + TPB - 1) / TPB, TPB, SH_BYTES>>>(
        x, h, w1, b1, w12, b12, w13, b13, w14, b14, w15, b15, w2, b2, out);
    h_stats<<<(N_ROWS + HS_ROWS - 1) / HS_ROWS, 128>>>(h);
    finalize<<<1, 32>>>(out);
}

// round 2
// speedup vs baseline: 1.3180x; 1.3180x over previous
#include <cuda_runtime.h>
#include <math.h>

#define N_ROWS 500000
#define TPB 512

typedef unsigned long long ull;

// ---------------- f32x2 packed helpers (Blackwell sm_103a) ----------------
__device__ __forceinline__ ull ffma2(ull a, ull b, ull c) {
    ull d;
    asm("fma.rn.f32x2 %0, %1, %2, %3;" : "=l"(d) : "l"(a), "l"(b), "l"(c));
    return d;
}
__device__ __forceinline__ ull pack2(float lo, float hi) {
    float2 t = make_float2(lo, hi);
    return *reinterpret_cast<ull*>(&t);
}
__device__ __forceinline__ float fold2(ull v) {
    float2 t = *reinterpret_cast<float2*>(&v);
    return t.x + t.y;
}

// ---------------- shared-memory layout (floats) ----------------
#define OFF_W1   0          // 100 x 200
#define OFF_B1   20000      // 100
#define OFF_W12  20100      // 50 x 100
#define OFF_B12  25100      // 50
#define OFF_W13  25152      // 30 x 152  (cols [0..49]=z2, [52..151]=h)
#define OFF_B13  29712      // 30
#define OFF_W14  29744      // 20 x 32
#define OFF_B14  30384      // 20
#define OFF_W15  30408      // 40 x 120  (cols [0..19]=z4, [20..119]=h)
#define OFF_B15  35208      // 40
#define OFF_W2   35248      // 100 x 40
#define OFF_B2   39248      // 100
#define SH_FLOATS 39348
#define SH_BYTES (SH_FLOATS * 4)

#define OUT_SCALAR ((size_t)N_ROWS * 100)

// ---------------- global accumulators ----------------
__device__ double g_p0;
__device__ double g_sq;
__device__ double g_diff;
__device__ double g_mu[100];

__global__ void init_kernel() {
    int t = threadIdx.x;
    if (t == 0) { g_p0 = 0.0; g_sq = 0.0; g_diff = 0.0; }
    if (t < 100) g_mu[t] = 0.0;
}

// ---------------- fused MLP, thread-per-row, f32x2 packed ----------------
__global__ void __launch_bounds__(TPB, 1) fused_mlp(
    const float* __restrict__ x, const float* __restrict__ h,
    const float* __restrict__ w1,  const float* __restrict__ b1,
    const float* __restrict__ w12, const float* __restrict__ b12,
    const float* __restrict__ w13, const float* __restrict__ b13,
    const float* __restrict__ w14, const float* __restrict__ b14,
    const float* __restrict__ w15, const float* __restrict__ b15,
    const float* __restrict__ w2,  const float* __restrict__ b2,
    float* __restrict__ out)
{
    extern __shared__ float s[];
    const int tid = threadIdx.x;

    // cooperative weight staging
    for (int i = tid; i < 20000; i += TPB) s[OFF_W1 + i] = w1[i];
    for (int i = tid; i < 100;   i += TPB) s[OFF_B1 + i] = b1[i];
    for (int i = tid; i < 5000;  i += TPB) s[OFF_W12 + i] = w12[i];
    for (int i = tid; i < 50;    i += TPB) s[OFF_B12 + i] = b12[i];
    for (int i = tid; i < 4560;  i += TPB) s[OFF_W13 + i] = 0.0f;  // pad cols zeroed
    __syncthreads();
    for (int i = tid; i < 4500;  i += TPB) {
        int r_ = i / 150, c = i % 150;
        s[OFF_W13 + r_ * 152 + (c < 50 ? c : c + 2)] = w13[i];
    }
    for (int i = tid; i < 30;    i += TPB) s[OFF_B13 + i] = b13[i];
    for (int i = tid; i < 640;   i += TPB) s[OFF_W14 + i] = 0.0f;
    __syncthreads();
    for (int i = tid; i < 600;   i += TPB) {
        int r_ = i / 30, c = i % 30;
        s[OFF_W14 + r_ * 32 + c] = w14[i];
    }
    for (int i = tid; i < 20;    i += TPB) s[OFF_B14 + i] = b14[i];
    for (int i = tid; i < 4800;  i += TPB) s[OFF_W15 + i] = w15[i];
    for (int i = tid; i < 40;    i += TPB) s[OFF_B15 + i] = b15[i];
    for (int i = tid; i < 4000;  i += TPB) s[OFF_W2 + i] = w2[i];
    for (int i = tid; i < 100;   i += TPB) s[OFF_B2 + i] = b2[i];
    __syncthreads();

    const int row = blockIdx.x * TPB + tid;
    float p0 = 0.0f;

    if (row < N_ROWS) {
        const float* xr = x + (size_t)row * 100;
        const float* hr = h + (size_t)row * 100;

        // ================= layers 1+2 fused, 5 chunks of 20 L1 outputs ====
        float z2[50];
        #pragma unroll
        for (int m = 0; m < 50; m++) z2[m] = s[OFF_B12 + m];

        #pragma unroll 1
        for (int chunk = 0; chunk < 5; ++chunk) {
            const float* wbase = s + OFF_W1 + chunk * 20 * 200;
            const float* bbase = s + OFF_B1 + chunk * 20;
            ull acc[20];
            #pragma unroll
            for (int j = 0; j < 20; j++) acc[j] = pack2(bbase[j], 0.0f);

            // x contribution
            #pragma unroll 1
            for (int k = 0; k < 100; k += 4) {
                ulonglong2 in2 = *(const ulonglong2*)(xr + k);
                #pragma unroll
                for (int j = 0; j < 20; j++) {
                    ulonglong2 w = *(const ulonglong2*)(wbase + j * 200 + k);
                    acc[j] = ffma2(w.x, in2.x, acc[j]);
                    acc[j] = ffma2(w.y, in2.y, acc[j]);
                }
            }
            // h contribution
            #pragma unroll 1
            for (int k = 0; k < 100; k += 4) {
                ulonglong2 in2 = *(const ulonglong2*)(hr + k);
                #pragma unroll
                for (int j = 0; j < 20; j++) {
                    ulonglong2 w = *(const ulonglong2*)(wbase + j * 200 + 100 + k);
                    acc[j] = ffma2(w.x, in2.x, acc[j]);
                    acc[j] = ffma2(w.y, in2.y, acc[j]);
                }
            }
            // relu + pack layer-1 activations
            ull ap[10];
            #pragma unroll
            for (int t = 0; t < 10; t++) {
                float a0 = fmaxf(fold2(acc[2 * t]),     0.0f);
                float a1 = fmaxf(fold2(acc[2 * t + 1]), 0.0f);
                ap[t] = pack2(a0, a1);
            }
            // layer-2 partial accumulate: z2 += W12[:, chunk*20 .. +20] @ a
            const float* w12b = s + OFF_W12 + chunk * 20;
            #pragma unroll
            for (int m = 0; m < 50; m++) {
                ull t2 = 0ull;
                #pragma unroll
                for (int j = 0; j < 5; j++) {
                    ulonglong2 w = *(const ulonglong2*)(w12b + m * 100 + j * 4);
                    t2 = ffma2(w.x, ap[2 * j],     t2);
                    t2 = ffma2(w.y, ap[2 * j + 1], t2);
                }
                z2[m] += fold2(t2);
            }
        }
        #pragma unroll
        for (int m = 0; m < 50; m++) z2[m] = fmaxf(z2[m], 0.0f);

        // ================= layer 3: z3 = relu(W13 @ [z2; h] + b13) =======
        ull zp[25];
        #pragma unroll
        for (int t = 0; t < 25; t++) zp[t] = pack2(z2[2 * t], z2[2 * t + 1]);

        float z3[30];
        #pragma unroll
        for (int half = 0; half < 2; ++half) {
            const int mb = half * 15;
            ull acc[15];
            #pragma unroll
            for (int m = 0; m < 15; m++) acc[m] = pack2(s[OFF_B13 + mb + m], 0.0f);
            #pragma unroll
            for (int j = 0; j < 25; j++) {
                #pragma unroll
                for (int m = 0; m < 15; m++) {
                    ull w = *(const ull*)(s + OFF_W13 + (mb + m) * 152 + j * 2);
                    acc[m] = ffma2(w, zp[j], acc[m]);
                }
            }
            #pragma unroll 1
            for (int k = 0; k < 100; k += 4) {
                ulonglong2 in2 = *(const ulonglong2*)(hr + k);
                #pragma unroll
                for (int m = 0; m < 15; m++) {
                    ulonglong2 w = *(const ulonglong2*)(s + OFF_W13 + (mb + m) * 152 + 52 + k);
                    acc[m] = ffma2(w.x, in2.x, acc[m]);
                    acc[m] = ffma2(w.y, in2.y, acc[m]);
                }
            }
            #pragma unroll
            for (int m = 0; m < 15; m++) z3[mb + m] = fmaxf(fold2(acc[m]), 0.0f);
        }

        // ================= layer 4: z4 = relu(W14 @ z3 + b14) ============
        ull zp3[15];
        #pragma unroll
        for (int t = 0; t < 15; t++) zp3[t] = pack2(z3[2 * t], z3[2 * t + 1]);

        float z4[20];
        #pragma unroll
        for (int m = 0; m < 20; m++) {
            ull t2 = pack2(s[OFF_B14 + m], 0.0f);
            #pragma unroll
            for (int j = 0; j < 15; j++) {
                ull w = *(const ull*)(s + OFF_W14 + m * 32 + j * 2);
                t2 = ffma2(w, zp3[j], t2);
            }
            z4[m] = fmaxf(fold2(t2), 0.0f);
        }

        // ================= layer 5: z5 = relu(W15 @ [z4; h] + b15) =======
        ull zp4[10];
        #pragma unroll
        for (int t = 0; t < 10; t++) zp4[t] = pack2(z4[2 * t], z4[2 * t + 1]);

        float z5[40];
        #pragma unroll
        for (int half = 0; half < 2; ++half) {
            const int mb = half * 20;
            ull acc[20];
            #pragma unroll
            for (int m = 0; m < 20; m++) acc[m] = pack2(s[OFF_B15 + mb + m], 0.0f);
            #pragma unroll
            for (int j = 0; j < 10; j++) {
                #pragma unroll
                for (int m = 0; m < 20; m++) {
                    ull w = *(const ull*)(s + OFF_W15 + (mb + m) * 120 + j * 2);
                    acc[m] = ffma2(w, zp4[j], acc[m]);
                }
            }
            #pragma unroll 1
            for (int k = 0; k < 100; k += 4) {
                ulonglong2 in2 = *(const ulonglong2*)(hr + k);
                #pragma unroll
                for (int m = 0; m < 20; m++) {
                    ulonglong2 w = *(const ulonglong2*)(s + OFF_W15 + (mb + m) * 120 + 20 + k);
                    acc[m] = ffma2(w.x, in2.x, acc[m]);
                    acc[m] = ffma2(w.y, in2.y, acc[m]);
                }
            }
            #pragma unroll
            for (int m = 0; m < 20; m++) z5[mb + m] = fmaxf(fold2(acc[m]), 0.0f);
        }

        // ================= output layer + fused part0 ====================
        ull zp5[20];
        #pragma unroll
        for (int t = 0; t < 20; t++) zp5[t] = pack2(z5[2 * t], z5[2 * t + 1]);

        float* outr = out + (size_t)row * 100;
        const float* xn = x + (size_t)(row + 1) * 100;
        const bool hasnext = (row + 1 < N_ROWS);
        ull p0acc = 0ull;

        #pragma unroll 1
        for (int c = 0; c < 25; c++) {
            ull a0 = pack2(s[OFF_B2 + 4 * c + 0], 0.0f);
            ull a1 = pack2(s[OFF_B2 + 4 * c + 1], 0.0f);
            ull a2 = pack2(s[OFF_B2 + 4 * c + 2], 0.0f);
            ull a3 = pack2(s[OFF_B2 + 4 * c + 3], 0.0f);
            const float* wr = s + OFF_W2 + 4 * c * 40;
            #pragma unroll
            for (int j = 0; j < 10; j++) {
                ulonglong2 w0 = *(const ulonglong2*)(wr +   0 + j * 4);
                ulonglong2 w1_ = *(const ulonglong2*)(wr +  40 + j * 4);
                ulonglong2 w2_ = *(const ulonglong2*)(wr +  80 + j * 4);
                ulonglong2 w3_ = *(const ulonglong2*)(wr + 120 + j * 4);
                a0 = ffma2(w0.x,  zp5[2 * j], a0); a0 = ffma2(w0.y,  zp5[2 * j + 1], a0);
                a1 = ffma2(w1_.x, zp5[2 * j], a1); a1 = ffma2(w1_.y, zp5[2 * j + 1], a1);
                a2 = ffma2(w2_.x, zp5[2 * j], a2); a2 = ffma2(w2_.y, zp5[2 * j + 1], a2);
                a3 = ffma2(w3_.x, zp5[2 * j], a3); a3 = ffma2(w3_.y, zp5[2 * j + 1], a3);
            }
            float4 v = make_float4(fold2(a0), fold2(a1), fold2(a2), fold2(a3));
            *(float4*)(outr + 4 * c) = v;
            if (hasnext) {
                float4 xv = *(const float4*)(xn + 4 * c);
                ull d01 = pack2(v.x - xv.x, v.y - xv.y);
                ull d23 = pack2(v.z - xv.z, v.w - xv.w);
                p0acc = ffma2(d01, d01, p0acc);
                p0acc = ffma2(d23, d23, p0acc);
            }
        }
        p0 = fold2(p0acc);
    }

    // ---- block reduction of part0, one double atomic per CTA ----
    #pragma unroll
    for (int o = 16; o > 0; o >>= 1) p0 += __shfl_down_sync(0xffffffffu, p0, o);
    __shared__ float red[TPB / 32];
    const int wid = tid >> 5, lane = tid & 31;
    if (lane == 0) red[wid] = p0;
    __syncthreads();
    if (tid == 0) {
        float acc = 0.0f;
        #pragma unroll
        for (int i = 0; i < TPB / 32; i++) acc += red[i];
        atomicAdd(&g_p0, (double)acc);
    }
}

// ---------------- h statistics (float inner accumulation) ----------------
#define HS_ROWS 1024
__global__ void h_stats(const float* __restrict__ h) {
    const int col = threadIdx.x;  // 128 threads, cols 0..99 active
    const long long r0 = (long long)blockIdx.x * HS_ROWS;
    long long r1 = r0 + HS_ROWS; if (r1 > N_ROWS) r1 = N_ROWS;

    float csum = 0.0f, sq = 0.0f, dif = 0.0f;
    if (col < 100 && r0 < N_ROWS) {
        float prev = h[r0 * 100 + col];
        csum = prev; sq = prev * prev;
        #pragma unroll 4
        for (long long r = r0 + 1; r < r1; ++r) {
            float v = h[r * 100 + col];
            csum += v;
            sq   = fmaf(v, v, sq);
            dif  += fabsf(v - prev);
            prev = v;
        }
        if (r1 < N_ROWS) {   // bridge pair (r1-1, r1)
            float v = h[r1 * 100 + col];
            dif += fabsf(v - prev);
        }
        atomicAdd(&g_mu[col], (double)csum);
    }

    __shared__ float ssq[128], sdf[128];
    ssq[threadIdx.x] = sq; sdf[threadIdx.x] = dif;
    __syncthreads();
    for (int off = 64; off > 0; off >>= 1) {
        if (threadIdx.x < off) {
            ssq[threadIdx.x] += ssq[threadIdx.x + off];
            sdf[threadIdx.x] += sdf[threadIdx.x + off];
        }
        __syncthreads();
    }
    if (threadIdx.x == 0) {
        atomicAdd(&g_sq,   (double)ssq[0]);
        atomicAdd(&g_diff, (double)sdf[0]);
    }
}

// ---------------- finalize scalars (parallel) ----------------
__global__ void finalize(float* __restrict__ out) {
    __shared__ double sm[128];
    const int t = threadIdx.x;
    sm[t] = (t < 100) ? fabs(g_mu[t] / (double)N_ROWS) : 0.0;
    __syncthreads();
    for (int off = 64; off > 0; off >>= 1) {
        if (t < off) sm[t] += sm[t + off];
        __syncthreads();
    }
    if (t == 0) {
        out[OUT_SCALAR + 0] = (float)(sqrt(g_p0) / (double)(N_ROWS - 1));
        out[OUT_SCALAR + 1] = (float)(sm[0] / 100.0);
        out[OUT_SCALAR + 2] = (float)fabs(g_sq / (double)N_ROWS / 100.0 - 1.0);
        out[OUT_SCALAR + 3] = (float)(g_diff / (double)(N_ROWS - 1) / 100.0);
    }
}

// ---------------- launch ----------------
extern "C" void kernel_launch(void* const* d_in, const int* in_sizes, int n_in,
                              void* d_out, int out_size) {
    const float* x   = (const float*)d_in[0];
    const float* h   = (const float*)d_in[1];
    const float* w1  = (const float*)d_in[2];
    const float* b1  = (const float*)d_in[3];
    const float* w12 = (const float*)d_in[4];
    const float* b12 = (const float*)d_in[5];
    const float* w13 = (const float*)d_in[6];
    const float* b13 = (const float*)d_in[7];
    const float* w14 = (const float*)d_in[8];
    const float* b14 = (const float*)d_in[9];
    const float* w15 = (const float*)d_in[10];
    const float* b15 = (const float*)d_in[11];
    const float* w2  = (const float*)d_in[12];
    const float* b2  = (const float*)d_in[13];
    float* out = (float*)d_out;

    (void)in_sizes; (void)n_in; (void)out_size;

    cudaFuncSetAttribute(fused_mlp, cudaFuncAttributeMaxDynamicSharedMemorySize, SH_BYTES);

    init_kernel<<<1, 128>>>();
    fused_mlp<<<(N_ROWS + TPB - 1) / TPB, TPB, SH_BYTES>>>(
        x, h, w1, b1, w12, b12, w13, b13, w14, b14, w15, b15, w2, b2, out);
    h_stats<<<(N_ROWS + HS_ROWS - 1) / HS_ROWS, 128>>>(h);
    finalize<<<1, 32 * 4>>>(out);
}

// round 4
// speedup vs baseline: 1.4833x; 1.1255x over previous
#include <cuda_runtime.h>
#include <math.h>

#define N_ROWS 500000
#define TPB 256

typedef unsigned long long ull;

// ---------------- f32x2 packed helpers (Blackwell sm_103a) ----------------
__device__ __forceinline__ ull ffma2(ull a, ull b, ull c) {
    ull d;
    asm("fma.rn.f32x2 %0, %1, %2, %3;" : "=l"(d) : "l"(a), "l"(b), "l"(c));
    return d;
}
__device__ __forceinline__ ull pack2(float lo, float hi) {
    float2 t = make_float2(lo, hi);
    return *reinterpret_cast<ull*>(&t);
}
__device__ __forceinline__ ull bcast2(float v) { return pack2(v, v); }
__device__ __forceinline__ float lo2(ull v) { return reinterpret_cast<float2*>(&v)->x; }
__device__ __forceinline__ float hi2(ull v) { return reinterpret_cast<float2*>(&v)->y; }
__device__ __forceinline__ float fold2(ull v) {
    float2 t = *reinterpret_cast<float2*>(&v);
    return t.x + t.y;
}
__device__ __forceinline__ ull relu2(ull v) {
    float2 t = *reinterpret_cast<float2*>(&v);
    t.x = fmaxf(t.x, 0.0f); t.y = fmaxf(t.y, 0.0f);
    return *reinterpret_cast<ull*>(&t);
}

// -------- shared-memory layout (floats; every 16B load lands 16B-aligned) --
// W1T stored 200 rows x 104 cols: cols [0..49] = outputs 0..49 (pass 0),
// cols [52..101] = outputs 50..99 (pass 1). Row stride 416B, pass-1 offset
// 208B — both multiples of 16.
#define OFF_W1T  0          // 200 x 104
#define OFF_B1   20800      // 100
#define OFF_W12T 20900      // 100 x 52   (W12T[k][n] = w12[n][k], pad 2)
#define OFF_B12  26100      // 50
#define OFF_W13  26152      // 30 x 152   (cols [0..49]=z2, [52..151]=h)
#define OFF_B13  30712      // 30
#define OFF_W14  30744      // 20 x 32
#define OFF_B14  31384      // 20
#define OFF_W15  31404      // 40 x 120   (cols [0..19]=z4, [20..119]=h)
#define OFF_B15  36204      // 40
#define OFF_W2   36244      // 100 x 40
#define OFF_B2   40244      // 100
#define SH_FLOATS 40344
#define SH_BYTES (SH_FLOATS * 4)

#define OUT_SCALAR ((size_t)N_ROWS * 100)

// ---------------- global accumulators ----------------
__device__ double g_p0;
__device__ double g_sq;
__device__ double g_diff;
__device__ double g_mu[100];

__global__ void init_kernel() {
    int t = threadIdx.x;
    if (t == 0) { g_p0 = 0.0; g_sq = 0.0; g_diff = 0.0; }
    if (t < 100) g_mu[t] = 0.0;
}

// ---------------- fused MLP, thread-per-row, output-packed f32x2 ----------
__global__ void __launch_bounds__(TPB, 1) fused_mlp(
    const float* __restrict__ x, const float* __restrict__ h,
    const float* __restrict__ w1,  const float* __restrict__ b1,
    const float* __restrict__ w12, const float* __restrict__ b12,
    const float* __restrict__ w13, const float* __restrict__ b13,
    const float* __restrict__ w14, const float* __restrict__ b14,
    const float* __restrict__ w15, const float* __restrict__ b15,
    const float* __restrict__ w2,  const float* __restrict__ b2,
    float* __restrict__ out)
{
    extern __shared__ float s[];
    const int tid = threadIdx.x;

    // ---- phase A: zero padded regions ----
    for (int i = tid; i < 20800; i += TPB) s[OFF_W1T + i] = 0.0f;
    for (int i = tid; i < 5200;  i += TPB) s[OFF_W12T + i] = 0.0f;
    for (int i = tid; i < 4560;  i += TPB) s[OFF_W13 + i] = 0.0f;
    for (int i = tid; i < 640;   i += TPB) s[OFF_W14 + i] = 0.0f;
    __syncthreads();

    // ---- phase B: fill ----
    for (int i = tid; i < 20000; i += TPB) {         // W1 transposed, split cols
        int k = i / 100, m = i % 100;
        int col = (m < 50) ? m : (m + 2);
        s[OFF_W1T + k * 104 + col] = w1[m * 200 + k];
    }
    for (int i = tid; i < 100;   i += TPB) s[OFF_B1 + i] = b1[i];
    for (int i = tid; i < 5000;  i += TPB) {         // W12 transposed
        int n = i / 100, k = i % 100;
        s[OFF_W12T + k * 52 + n] = w12[i];
    }
    for (int i = tid; i < 50;    i += TPB) s[OFF_B12 + i] = b12[i];
    for (int i = tid; i < 4500;  i += TPB) {
        int r_ = i / 150, c = i % 150;
        s[OFF_W13 + r_ * 152 + (c < 50 ? c : c + 2)] = w13[i];
    }
    for (int i = tid; i < 30;    i += TPB) s[OFF_B13 + i] = b13[i];
    for (int i = tid; i < 600;   i += TPB) {
        int r_ = i / 30, c = i % 30;
        s[OFF_W14 + r_ * 32 + c] = w14[i];
    }
    for (int i = tid; i < 20;    i += TPB) s[OFF_B14 + i] = b14[i];
    for (int i = tid; i < 4800;  i += TPB) s[OFF_W15 + i] = w15[i];
    for (int i = tid; i < 40;    i += TPB) s[OFF_B15 + i] = b15[i];
    for (int i = tid; i < 4000;  i += TPB) s[OFF_W2 + i] = w2[i];
    for (int i = tid; i < 100;   i += TPB) s[OFF_B2 + i] = b2[i];
    __syncthreads();

    const int row = blockIdx.x * TPB + tid;
    float p0 = 0.0f;

    if (row < N_ROWS) {
        const float* xr = x + (size_t)row * 100;
        const float* hr = h + (size_t)row * 100;

        // ====== layers 1+2 fused; L1 output-packed, 2 passes of 50 =======
        ull z2p[25];
        #pragma unroll
        for (int t = 0; t < 25; t++) z2p[t] = pack2(s[OFF_B12 + 2 * t], s[OFF_B12 + 2 * t + 1]);

        #pragma unroll 1
        for (int pass = 0; pass < 2; ++pass) {
            const int mb = pass * 50;        // logical output base
            const int mboff = pass * 52;     // smem column offset (16B-aligned)
            ull acc[25];
            #pragma unroll
            for (int j = 0; j < 25; j++)
                acc[j] = pack2(s[OFF_B1 + mb + 2 * j], s[OFF_B1 + mb + 2 * j + 1]);

            // x contribution: W1T rows 0..99
            #pragma unroll 1
            for (int k = 0; k < 100; k += 4) {
                float4 v4 = *(const float4*)(xr + k);
                const float* wr0 = s + OFF_W1T + (size_t)k * 104 + mboff;
                #pragma unroll
                for (int i = 0; i < 4; i++) {
                    float vi = (i == 0) ? v4.x : (i == 1) ? v4.y : (i == 2) ? v4.z : v4.w;
                    ull vv = bcast2(vi);
                    const float* wr = wr0 + i * 104;
                    #pragma unroll
                    for (int j = 0; j < 12; j++) {
                        ulonglong2 w = *(const ulonglong2*)(wr + 4 * j);
                        acc[2 * j]     = ffma2(w.x, vv, acc[2 * j]);
                        acc[2 * j + 1] = ffma2(w.y, vv, acc[2 * j + 1]);
                    }
                    ull wl = *(const ull*)(wr + 48);
                    acc[24] = ffma2(wl, vv, acc[24]);
                }
            }
            // h contribution: W1T rows 100..199
            #pragma unroll 1
            for (int k = 0; k < 100; k += 4) {
                float4 v4 = *(const float4*)(hr + k);
                const float* wr0 = s + OFF_W1T + (size_t)(100 + k) * 104 + mboff;
                #pragma unroll
                for (int i = 0; i < 4; i++) {
                    float vi = (i == 0) ? v4.x : (i == 1) ? v4.y : (i == 2) ? v4.z : v4.w;
                    ull vv = bcast2(vi);
                    const float* wr = wr0 + i * 104;
                    #pragma unroll
                    for (int j = 0; j < 12; j++) {
                        ulonglong2 w = *(const ulonglong2*)(wr + 4 * j);
                        acc[2 * j]     = ffma2(w.x, vv, acc[2 * j]);
                        acc[2 * j + 1] = ffma2(w.y, vv, acc[2 * j + 1]);
                    }
                    ull wl = *(const ull*)(wr + 48);
                    acc[24] = ffma2(wl, vv, acc[24]);
                }
            }
            // relu (packed)
            #pragma unroll
            for (int j = 0; j < 25; j++) acc[j] = relu2(acc[j]);

            // layer-2 partial: z2p += W12T[k][:] * z1[k]
            #pragma unroll 1
            for (int j = 0; j < 25; j++) {
                #pragma unroll
                for (int half = 0; half < 2; ++half) {
                    float z = half ? hi2(acc[j]) : lo2(acc[j]);
                    ull zz = bcast2(z);
                    const float* wr = s + OFF_W12T + (size_t)(mb + 2 * j + half) * 52;
                    #pragma unroll
                    for (int t = 0; t < 12; t++) {
                        ulonglong2 w = *(const ulonglong2*)(wr + 4 * t);
                        z2p[2 * t]     = ffma2(w.x, zz, z2p[2 * t]);
                        z2p[2 * t + 1] = ffma2(w.y, zz, z2p[2 * t + 1]);
                    }
                    ull wl = *(const ull*)(wr + 48);
                    z2p[24] = ffma2(wl, zz, z2p[24]);
                }
            }
        }
        #pragma unroll
        for (int t = 0; t < 25; t++) z2p[t] = relu2(z2p[t]);

        // ====== layer 3: z3 = relu(W13 @ [z2; h] + b13), 2 halves ========
        float z3[30];
        #pragma unroll 1
        for (int half = 0; half < 2; ++half) {
            const int mb = half * 15;
            ull acc[15];
            #pragma unroll
            for (int m = 0; m < 15; m++) acc[m] = pack2(s[OFF_B13 + mb + m], 0.0f);
            #pragma unroll
            for (int j = 0; j < 12; j++) {
                #pragma unroll
                for (int m = 0; m < 15; m++) {
                    ulonglong2 w = *(const ulonglong2*)(s + OFF_W13 + (size_t)(mb + m) * 152 + 4 * j);
                    acc[m] = ffma2(w.x, z2p[2 * j], acc[m]);
                    acc[m] = ffma2(w.y, z2p[2 * j + 1], acc[m]);
                }
            }
            #pragma unroll
            for (int m = 0; m < 15; m++) {
                ull w = *(const ull*)(s + OFF_W13 + (size_t)(mb + m) * 152 + 48);
                acc[m] = ffma2(w, z2p[24], acc[m]);
            }
            #pragma unroll 1
            for (int k = 0; k < 100; k += 4) {
                ulonglong2 in2 = *(const ulonglong2*)(hr + k);
                #pragma unroll
                for (int m = 0; m < 15; m++) {
                    ulonglong2 w = *(const ulonglong2*)(s + OFF_W13 + (size_t)(mb + m) * 152 + 52 + k);
                    acc[m] = ffma2(w.x, in2.x, acc[m]);
                    acc[m] = ffma2(w.y, in2.y, acc[m]);
                }
            }
            #pragma unroll
            for (int m = 0; m < 15; m++) z3[mb + m] = fmaxf(fold2(acc[m]), 0.0f);
        }

        // ====== layer 4: z4 = relu(W14 @ z3 + b14) =======================
        ull zp3[15];
        #pragma unroll
        for (int t = 0; t < 15; t++) zp3[t] = pack2(z3[2 * t], z3[2 * t + 1]);

        float z4[20];
        #pragma unroll
        for (int m = 0; m < 20; m++) {
            ull t2 = pack2(s[OFF_B14 + m], 0.0f);
            const float* wr = s + OFF_W14 + m * 32;
            #pragma unroll
            for (int j = 0; j < 7; j++) {
                ulonglong2 w = *(const ulonglong2*)(wr + 4 * j);
                t2 = ffma2(w.x, zp3[2 * j], t2);
                t2 = ffma2(w.y, zp3[2 * j + 1], t2);
            }
            ull wl = *(const ull*)(wr + 28);
            t2 = ffma2(wl, zp3[14], t2);
            z4[m] = fmaxf(fold2(t2), 0.0f);
        }

        // ====== layer 5: z5 = relu(W15 @ [z4; h] + b15), 2 halves ========
        ull zp4[10];
        #pragma unroll
        for (int t = 0; t < 10; t++) zp4[t] = pack2(z4[2 * t], z4[2 * t + 1]);

        float z5[40];
        #pragma unroll 1
        for (int half = 0; half < 2; ++half) {
            const int mb = half * 20;
            ull acc[20];
            #pragma unroll
            for (int m = 0; m < 20; m++) acc[m] = pack2(s[OFF_B15 + mb + m], 0.0f);
            #pragma unroll
            for (int j = 0; j < 5; j++) {
                #pragma unroll
                for (int m = 0; m < 20; m++) {
                    ulonglong2 w = *(const ulonglong2*)(s + OFF_W15 + (size_t)(mb + m) * 120 + 4 * j);
                    acc[m] = ffma2(w.x, zp4[2 * j], acc[m]);
                    acc[m] = ffma2(w.y, zp4[2 * j + 1], acc[m]);
                }
            }
            #pragma unroll 1
            for (int k = 0; k < 100; k += 4) {
                ulonglong2 in2 = *(const ulonglong2*)(hr + k);
                #pragma unroll
                for (int m = 0; m < 20; m++) {
                    ulonglong2 w = *(const ulonglong2*)(s + OFF_W15 + (size_t)(mb + m) * 120 + 20 + k);
                    acc[m] = ffma2(w.x, in2.x, acc[m]);
                    acc[m] = ffma2(w.y, in2.y, acc[m]);
                }
            }
            #pragma unroll
            for (int m = 0; m < 20; m++) z5[mb + m] = fmaxf(fold2(acc[m]), 0.0f);
        }

        // ====== output layer + fused part0 ===============================
        ull zp5[20];
        #pragma unroll
        for (int t = 0; t < 20; t++) zp5[t] = pack2(z5[2 * t], z5[2 * t + 1]);

        float* outr = out + (size_t)row * 100;
        const float* xn = x + (size_t)(row + 1) * 100;
        const bool hasnext = (row + 1 < N_ROWS);
        ull p0acc = 0ull;

        #pragma unroll 1
        for (int c = 0; c < 25; c++) {
            ull a0 = pack2(s[OFF_B2 + 4 * c + 0], 0.0f);
            ull a1 = pack2(s[OFF_B2 + 4 * c + 1], 0.0f);
            ull a2 = pack2(s[OFF_B2 + 4 * c + 2], 0.0f);
            ull a3 = pack2(s[OFF_B2 + 4 * c + 3], 0.0f);
            const float* wr = s + OFF_W2 + (size_t)(4 * c) * 40;
            #pragma unroll
            for (int j = 0; j < 10; j++) {
                ulonglong2 w0  = *(const ulonglong2*)(wr +   0 + j * 4);
                ulonglong2 w1_ = *(const ulonglong2*)(wr +  40 + j * 4);
                ulonglong2 w2_ = *(const ulonglong2*)(wr +  80 + j * 4);
                ulonglong2 w3_ = *(const ulonglong2*)(wr + 120 + j * 4);
                a0 = ffma2(w0.x,  zp5[2 * j], a0); a0 = ffma2(w0.y,  zp5[2 * j + 1], a0);
                a1 = ffma2(w1_.x, zp5[2 * j], a1); a1 = ffma2(w1_.y, zp5[2 * j + 1], a1);
                a2 = ffma2(w2_.x, zp5[2 * j], a2); a2 = ffma2(w2_.y, zp5[2 * j + 1], a2);
                a3 = ffma2(w3_.x, zp5[2 * j], a3); a3 = ffma2(w3_.y, zp5[2 * j + 1], a3);
            }
            float4 v = make_float4(fold2(a0), fold2(a1), fold2(a2), fold2(a3));
            *(float4*)(outr + 4 * c) = v;
            if (hasnext) {
                float4 xv = *(const float4*)(xn + 4 * c);
                ull d01 = pack2(v.x - xv.x, v.y - xv.y);
                ull d23 = pack2(v.z - xv.z, v.w - xv.w);
                p0acc = ffma2(d01, d01, p0acc);
                p0acc = ffma2(d23, d23, p0acc);
            }
        }
        p0 = fold2(p0acc);
    }

    // ---- block reduction of part0, one double atomic per CTA ----
    #pragma unroll
    for (int o = 16; o > 0; o >>= 1) p0 += __shfl_down_sync(0xffffffffu, p0, o);
    __shared__ float red[TPB / 32];
    const int wid = tid >> 5, lane = tid & 31;
    if (lane == 0) red[wid] = p0;
    __syncthreads();
    if (tid == 0) {
        float acc = 0.0f;
        #pragma unroll
        for (int i = 0; i < TPB / 32; i++) acc += red[i];
        atomicAdd(&g_p0, (double)acc);
    }
}

// ---------------- h statistics (float inner accumulation) ----------------
#define HS_ROWS 512
__global__ void h_stats(const float* __restrict__ h) {
    const int col = threadIdx.x;  // 128 threads, cols 0..99 active
    const long long r0 = (long long)blockIdx.x * HS_ROWS;
    long long r1 = r0 + HS_ROWS; if (r1 > N_ROWS) r1 = N_ROWS;

    float csum = 0.0f, sq = 0.0f, dif = 0.0f;
    if (col < 100 && r0 < N_ROWS) {
        float prev = h[r0 * 100 + col];
        csum = prev; sq = prev * prev;
        #pragma unroll 8
        for (long long r = r0 + 1; r < r1; ++r) {
            float v = h[r * 100 + col];
            csum += v;
            sq   = fmaf(v, v, sq);
            dif  += fabsf(v - prev);
            prev = v;
        }
        if (r1 < N_ROWS) {   // bridge pair (r1-1, r1)
            float v = h[r1 * 100 + col];
            dif += fabsf(v - prev);
        }
        atomicAdd(&g_mu[col], (double)csum);
    }

    __shared__ float ssq[128], sdf[128];
    ssq[threadIdx.x] = sq; sdf[threadIdx.x] = dif;
    __syncthreads();
    for (int off = 64; off > 0; off >>= 1) {
        if (threadIdx.x < off) {
            ssq[threadIdx.x] += ssq[threadIdx.x + off];
            sdf[threadIdx.x] += sdf[threadIdx.x + off];
        }
        __syncthreads();
    }
    if (threadIdx.x == 0) {
        atomicAdd(&g_sq,   (double)ssq[0]);
        atomicAdd(&g_diff, (double)sdf[0]);
    }
}

// ---------------- finalize scalars (parallel) ----------------
__global__ void finalize(float* __restrict__ out) {
    __shared__ double sm[128];
    const int t = threadIdx.x;
    sm[t] = (t < 100) ? fabs(g_mu[t] / (double)N_ROWS) : 0.0;
    __syncthreads();
    for (int off = 64; off > 0; off >>= 1) {
        if (t < off) sm[t] += sm[t + off];
        __syncthreads();
    }
    if (t == 0) {
        out[OUT_SCALAR + 0] = (float)(sqrt(g_p0) / (double)(N_ROWS - 1));
        out[OUT_SCALAR + 1] = (float)(sm[0] / 100.0);
        out[OUT_SCALAR + 2] = (float)fabs(g_sq / (double)N_ROWS / 100.0 - 1.0);
        out[OUT_SCALAR + 3] = (float)(g_diff / (double)(N_ROWS - 1) / 100.0);
    }
}

// ---------------- launch ----------------
extern "C" void kernel_launch(void* const* d_in, const int* in_sizes, int n_in,
                              void* d_out, int out_size) {
    const float* x   = (const float*)d_in[0];
    const float* h   = (const float*)d_in[1];
    const float* w1  = (const float*)d_in[2];
    const float* b1  = (const float*)d_in[3];
    const float* w12 = (const float*)d_in[4];
    const float* b12 = (const float*)d_in[5];
    const float* w13 = (const float*)d_in[6];
    const float* b13 = (const float*)d_in[7];
    const float* w14 = (const float*)d_in[8];
    const float* b14 = (const float*)d_in[9];
    const float* w15 = (const float*)d_in[10];
    const float* b15 = (const float*)d_in[11];
    const float* w2  = (const float*)d_in[12];
    const float* b2  = (const float*)d_in[13];
    float* out = (float*)d_out;

    (void)in_sizes; (void)n_in; (void)out_size;

    cudaFuncSetAttribute(fused_mlp, cudaFuncAttributeMaxDynamicSharedMemorySize, SH_BYTES);

    init_kernel<<<1, 128>>>();
    fused_mlp<<<(N_ROWS + TPB - 1) / TPB, TPB, SH_BYTES>>>(
        x, h, w1, b1, w12, b12, w13, b13, w14, b14, w15, b15, w2, b2, out);
    h_stats<<<(N_ROWS + HS_ROWS - 1) / HS_ROWS, 128>>>(h);
    finalize<<<1, 32 * 4>>>(out);
}

// round 5
// speedup vs baseline: 1.7271x; 1.1643x over previous
#include <cuda_runtime.h>
#include <math.h>

#define N_ROWS 500000
#define TPB 512   // 2 threads per row -> 256 rows per CTA

typedef unsigned long long ull;

// ---------------- f32x2 packed helpers (Blackwell sm_103a) ----------------
__device__ __forceinline__ ull ffma2(ull a, ull b, ull c) {
    ull d;
    asm("fma.rn.f32x2 %0, %1, %2, %3;" : "=l"(d) : "l"(a), "l"(b), "l"(c));
    return d;
}
__device__ __forceinline__ ull pack2(float lo, float hi) {
    float2 t = make_float2(lo, hi);
    return *reinterpret_cast<ull*>(&t);
}
__device__ __forceinline__ ull bcast2(float v) { return pack2(v, v); }
__device__ __forceinline__ float lo2(ull v) { return reinterpret_cast<float2*>(&v)->x; }
__device__ __forceinline__ float hi2(ull v) { return reinterpret_cast<float2*>(&v)->y; }
__device__ __forceinline__ float fold2(ull v) {
    float2 t = *reinterpret_cast<float2*>(&v);
    return t.x + t.y;
}
__device__ __forceinline__ ull relu2(ull v) {
    float2 t = *reinterpret_cast<float2*>(&v);
    t.x = fmaxf(t.x, 0.0f); t.y = fmaxf(t.y, 0.0f);
    return *reinterpret_cast<ull*>(&t);
}
__device__ __forceinline__ ull shflx1(ull v) {   // exchange with pair mate
    return __shfl_xor_sync(0xffffffffu, v, 1);
}

// -------- shared-memory layout (floats; every LDS.128 lands 16B-aligned) --
// W1T : 200 x 104, cols [0..49]=outputs 0..49, [52..101]=outputs 50..99
// W12T: 100 x 56,  [k][n], z2 padded to 56 (pads 50..55)
// W13 : 30 x 156,  cols [0..55]=z2(padded 56), [56..155]=h
// W14 : 20 x 32,   z3 padded 32 (z3 c -> col c<15?c:c+1; pads 15,30,31)
// W15 : 40 x 124,  cols [0..23]=z4 padded 24 (c<10?c:c+2), [24..123]=h
// W2  : 100 x 40
#define OFF_W1T  0
#define OFF_B1   20800
#define OFF_W12T 20900
#define OFF_B12  26500
#define OFF_W13  26552
#define OFF_B13  31232
#define OFF_W14  31264
#define OFF_B14  31904
#define OFF_W15  31924
#define OFF_B15  36884
#define OFF_W2   36924
#define OFF_B2   40924
#define SH_FLOATS 41024
#define SH_BYTES (SH_FLOATS * 4)

#define OUT_SCALAR ((size_t)N_ROWS * 100)

// ---------------- global accumulators ----------------
__device__ double g_p0;
__device__ double g_sq;
__device__ double g_diff;
__device__ double g_mu[100];

__global__ void init_kernel() {
    int t = threadIdx.x;
    if (t == 0) { g_p0 = 0.0; g_sq = 0.0; g_diff = 0.0; }
    if (t < 100) g_mu[t] = 0.0;
}

// --------- fused MLP: one row per THREAD PAIR, output-split halves --------
__global__ void __launch_bounds__(TPB, 1) fused_mlp(
    const float* __restrict__ x, const float* __restrict__ h,
    const float* __restrict__ w1,  const float* __restrict__ b1,
    const float* __restrict__ w12, const float* __restrict__ b12,
    const float* __restrict__ w13, const float* __restrict__ b13,
    const float* __restrict__ w14, const float* __restrict__ b14,
    const float* __restrict__ w15, const float* __restrict__ b15,
    const float* __restrict__ w2,  const float* __restrict__ b2,
    float* __restrict__ out)
{
    extern __shared__ float s[];
    const int tid = threadIdx.x;

    // ---- phase A: zero padded regions ----
    for (int i = tid; i < 20800; i += TPB) s[OFF_W1T + i] = 0.0f;
    for (int i = tid; i < 5600;  i += TPB) s[OFF_W12T + i] = 0.0f;
    for (int i = tid; i < 4680;  i += TPB) s[OFF_W13 + i] = 0.0f;
    for (int i = tid; i < 640;   i += TPB) s[OFF_W14 + i] = 0.0f;
    for (int i = tid; i < 4960;  i += TPB) s[OFF_W15 + i] = 0.0f;
    __syncthreads();

    // ---- phase B: fill ----
    for (int i = tid; i < 20000; i += TPB) {        // W1 transposed, split cols
        int k = i / 100, m = i % 100;
        int col = (m < 50) ? m : (m + 2);
        s[OFF_W1T + k * 104 + col] = w1[m * 200 + k];
    }
    for (int i = tid; i < 100;   i += TPB) s[OFF_B1 + i] = b1[i];
    for (int i = tid; i < 5000;  i += TPB) {        // W12 transposed
        int n = i / 100, k = i % 100;
        s[OFF_W12T + k * 56 + n] = w12[i];
    }
    for (int i = tid; i < 50;    i += TPB) s[OFF_B12 + i] = b12[i];
    for (int i = tid; i < 4500;  i += TPB) {        // W13 with z2-pad remap
        int r_ = i / 150, c = i % 150;
        s[OFF_W13 + r_ * 156 + (c < 50 ? c : c + 6)] = w13[i];
    }
    for (int i = tid; i < 30;    i += TPB) s[OFF_B13 + i] = b13[i];
    for (int i = tid; i < 600;   i += TPB) {        // W14 with z3-pad remap
        int r_ = i / 30, c = i % 30;
        s[OFF_W14 + r_ * 32 + (c < 15 ? c : c + 1)] = w14[i];
    }
    for (int i = tid; i < 20;    i += TPB) s[OFF_B14 + i] = b14[i];
    for (int i = tid; i < 4800;  i += TPB) {        // W15 with z4-pad remap
        int r_ = i / 120, c = i % 120;
        int col = (c < 10) ? c : (c < 20) ? (c + 2) : (c + 4);
        s[OFF_W15 + r_ * 124 + col] = w15[i];
    }
    for (int i = tid; i < 40;    i += TPB) s[OFF_B15 + i] = b15[i];
    for (int i = tid; i < 4000;  i += TPB) s[OFF_W2 + i] = w2[i];
    for (int i = tid; i < 100;   i += TPB) s[OFF_B2 + i] = b2[i];
    __syncthreads();

    const int half = tid & 1;                 // 0: first-half outputs, 1: second
    int row = (blockIdx.x * TPB + tid) >> 1;
    const bool valid = (row < N_ROWS);
    if (!valid) row = N_ROWS - 1;             // clamp: pair stays converged

    const float* xr = x + (size_t)row * 100;
    const float* hr = h + (size_t)row * 100;

    // ====== layer 1: 50 outputs per thread (single streaming pass) =======
    ull aL1[25];
    {
        const int mbase = half * 50, mboff = half * 52;
        #pragma unroll
        for (int j = 0; j < 25; j++)
            aL1[j] = pack2(s[OFF_B1 + mbase + 2 * j], s[OFF_B1 + mbase + 2 * j + 1]);

        #pragma unroll 1
        for (int k = 0; k < 100; k += 4) {
            float4 v4 = *(const float4*)(xr + k);
            const float* wr0 = s + OFF_W1T + (size_t)k * 104 + mboff;
            #pragma unroll
            for (int i = 0; i < 4; i++) {
                float vi = (i == 0) ? v4.x : (i == 1) ? v4.y : (i == 2) ? v4.z : v4.w;
                ull vv = bcast2(vi);
                const float* wr = wr0 + i * 104;
                #pragma unroll
                for (int j = 0; j < 12; j++) {
                    ulonglong2 w = *(const ulonglong2*)(wr + 4 * j);
                    aL1[2 * j]     = ffma2(w.x, vv, aL1[2 * j]);
                    aL1[2 * j + 1] = ffma2(w.y, vv, aL1[2 * j + 1]);
                }
                ull wl = *(const ull*)(wr + 48);
                aL1[24] = ffma2(wl, vv, aL1[24]);
            }
        }
        #pragma unroll 1
        for (int k = 0; k < 100; k += 4) {
            float4 v4 = *(const float4*)(hr + k);
            const float* wr0 = s + OFF_W1T + (size_t)(100 + k) * 104 + mboff;
            #pragma unroll
            for (int i = 0; i < 4; i++) {
                float vi = (i == 0) ? v4.x : (i == 1) ? v4.y : (i == 2) ? v4.z : v4.w;
                ull vv = bcast2(vi);
                const float* wr = wr0 + i * 104;
                #pragma unroll
                for (int j = 0; j < 12; j++) {
                    ulonglong2 w = *(const ulonglong2*)(wr + 4 * j);
                    aL1[2 * j]     = ffma2(w.x, vv, aL1[2 * j]);
                    aL1[2 * j + 1] = ffma2(w.y, vv, aL1[2 * j + 1]);
                }
                ull wl = *(const ull*)(wr + 48);
                aL1[24] = ffma2(wl, vv, aL1[24]);
            }
        }
        #pragma unroll
        for (int j = 0; j < 25; j++) aL1[j] = relu2(aL1[j]);
    }

    // ====== layer 2: z2 cols [half*28, +28) per thread ====================
    ull z2p[14];
    {
        #pragma unroll
        for (int t = 0; t < 14; t++) {
            int c = half * 28 + 2 * t;
            float b0 = (c     < 50) ? s[OFF_B12 + c]     : 0.0f;
            float b1v = (c + 1 < 50) ? s[OFF_B12 + c + 1] : 0.0f;
            z2p[t] = pack2(b0, b1v);
        }
        const int kown = half * 50, koth = 50 - kown;
        const int coff = half * 28;
        #pragma unroll 1
        for (int j = 0; j < 25; j++) {
            ull own = aL1[j];
            ull oth = shflx1(own);
            float zs[4] = { lo2(own), hi2(own), lo2(oth), hi2(oth) };
            int   ks[4] = { kown + 2 * j, kown + 2 * j + 1, koth + 2 * j, koth + 2 * j + 1 };
            #pragma unroll
            for (int q = 0; q < 4; q++) {
                ull zz = bcast2(zs[q]);
                const float* wr = s + OFF_W12T + (size_t)ks[q] * 56 + coff;
                #pragma unroll
                for (int t = 0; t < 7; t++) {
                    ulonglong2 w = *(const ulonglong2*)(wr + 4 * t);
                    z2p[2 * t]     = ffma2(w.x, zz, z2p[2 * t]);
                    z2p[2 * t + 1] = ffma2(w.y, zz, z2p[2 * t + 1]);
                }
            }
        }
        #pragma unroll
        for (int t = 0; t < 14; t++) z2p[t] = relu2(z2p[t]);
    }

    // ====== layer 3: 15 outputs per thread ================================
    float z3a[16];
    {
        ull pz2[14];
        #pragma unroll
        for (int t = 0; t < 14; t++) pz2[t] = shflx1(z2p[t]);
        const int ownoff = half * 28, othoff = 28 - ownoff;

        ull acc3[15];
        #pragma unroll
        for (int m = 0; m < 15; m++) {
            int mm = half * 15 + m;
            const float* base = s + OFF_W13 + (size_t)mm * 156;
            ull a = pack2(s[OFF_B13 + mm], 0.0f);
            #pragma unroll
            for (int t = 0; t < 7; t++) {
                ulonglong2 w = *(const ulonglong2*)(base + ownoff + 4 * t);
                a = ffma2(w.x, z2p[2 * t], a);
                a = ffma2(w.y, z2p[2 * t + 1], a);
            }
            #pragma unroll
            for (int t = 0; t < 7; t++) {
                ulonglong2 w = *(const ulonglong2*)(base + othoff + 4 * t);
                a = ffma2(w.x, pz2[2 * t], a);
                a = ffma2(w.y, pz2[2 * t + 1], a);
            }
            acc3[m] = a;
        }
        #pragma unroll 1
        for (int k = 0; k < 100; k += 4) {
            ulonglong2 in2 = *(const ulonglong2*)(hr + k);
            #pragma unroll
            for (int m = 0; m < 15; m++) {
                int mm = half * 15 + m;
                ulonglong2 w = *(const ulonglong2*)(s + OFF_W13 + (size_t)mm * 156 + 56 + k);
                acc3[m] = ffma2(w.x, in2.x, acc3[m]);
                acc3[m] = ffma2(w.y, in2.y, acc3[m]);
            }
        }
        #pragma unroll
        for (int m = 0; m < 15; m++) z3a[m] = fmaxf(fold2(acc3[m]), 0.0f);
        z3a[15] = 0.0f;
    }

    // ====== layer 4: 10 outputs per thread ================================
    float z4a[12];
    {
        ull zp3[8];
        #pragma unroll
        for (int t = 0; t < 8; t++) zp3[t] = pack2(z3a[2 * t], z3a[2 * t + 1]);
        ull pz3[8];
        #pragma unroll
        for (int t = 0; t < 8; t++) pz3[t] = shflx1(zp3[t]);
        const int ownoff = half * 16, othoff = 16 - ownoff;

        #pragma unroll
        for (int m = 0; m < 10; m++) {
            int mm = half * 10 + m;
            const float* base = s + OFF_W14 + (size_t)mm * 32;
            ull a = pack2(s[OFF_B14 + mm], 0.0f);
            #pragma unroll
            for (int t = 0; t < 4; t++) {
                ulonglong2 w = *(const ulonglong2*)(base + ownoff + 4 * t);
                a = ffma2(w.x, zp3[2 * t], a);
                a = ffma2(w.y, zp3[2 * t + 1], a);
            }
            #pragma unroll
            for (int t = 0; t < 4; t++) {
                ulonglong2 w = *(const ulonglong2*)(base + othoff + 4 * t);
                a = ffma2(w.x, pz3[2 * t], a);
                a = ffma2(w.y, pz3[2 * t + 1], a);
            }
            z4a[m] = fmaxf(fold2(a), 0.0f);
        }
        z4a[10] = 0.0f; z4a[11] = 0.0f;
    }

    // ====== layer 5: 20 outputs per thread ================================
    float z5a[20];
    {
        ull zp4[6];
        #pragma unroll
        for (int t = 0; t < 6; t++) zp4[t] = pack2(z4a[2 * t], z4a[2 * t + 1]);
        ull pz4[6];
        #pragma unroll
        for (int t = 0; t < 6; t++) pz4[t] = shflx1(zp4[t]);
        const int ownoff = half * 12, othoff = 12 - ownoff;

        ull acc5[20];
        #pragma unroll
        for (int m = 0; m < 20; m++) {
            int mm = half * 20 + m;
            const float* base = s + OFF_W15 + (size_t)mm * 124;
            ull a = pack2(s[OFF_B15 + mm], 0.0f);
            #pragma unroll
            for (int t = 0; t < 3; t++) {
                ulonglong2 w = *(const ulonglong2*)(base + ownoff + 4 * t);
                a = ffma2(w.x, zp4[2 * t], a);
                a = ffma2(w.y, zp4[2 * t + 1], a);
            }
            #pragma unroll
            for (int t = 0; t < 3; t++) {
                ulonglong2 w = *(const ulonglong2*)(base + othoff + 4 * t);
                a = ffma2(w.x, pz4[2 * t], a);
                a = ffma2(w.y, pz4[2 * t + 1], a);
            }
            acc5[m] = a;
        }
        #pragma unroll 1
        for (int k = 0; k < 100; k += 4) {
            ulonglong2 in2 = *(const ulonglong2*)(hr + k);
            #pragma unroll
            for (int m = 0; m < 20; m++) {
                int mm = half * 20 + m;
                ulonglong2 w = *(const ulonglong2*)(s + OFF_W15 + (size_t)mm * 124 + 24 + k);
                acc5[m] = ffma2(w.x, in2.x, acc5[m]);
                acc5[m] = ffma2(w.y, in2.y, acc5[m]);
            }
        }
        #pragma unroll
        for (int m = 0; m < 20; m++) z5a[m] = fmaxf(fold2(acc5[m]), 0.0f);
    }

    // ====== output layer: 50 outputs per thread + fused part0 =============
    float p0 = 0.0f;
    {
        ull zp5[10];
        #pragma unroll
        for (int t = 0; t < 10; t++) zp5[t] = pack2(z5a[2 * t], z5a[2 * t + 1]);
        ull pz5[10];
        #pragma unroll
        for (int t = 0; t < 10; t++) pz5[t] = shflx1(zp5[t]);
        const int ownoff = half * 20, othoff = 20 - ownoff;

        float* outr = out + (size_t)row * 100;
        const float* xn = x + (size_t)(row + 1) * 100;
        const bool hasnext = valid && (row + 1 < N_ROWS);
        ull p0acc = 0ull;

        // 12 aligned float4 chunks
        #pragma unroll 1
        for (int c = 0; c < 12; c++) {
            const int col = half * 52 + 4 * c;   // even: 0..44, odd: 52..96
            float fv[4];
            #pragma unroll
            for (int q = 0; q < 4; q++) {
                int mm = col + q;
                ull a = pack2(s[OFF_B2 + mm], 0.0f);
                const float* wr = s + OFF_W2 + (size_t)mm * 40;
                #pragma unroll
                for (int t = 0; t < 5; t++) {
                    ulonglong2 w = *(const ulonglong2*)(wr + ownoff + 4 * t);
                    a = ffma2(w.x, zp5[2 * t], a);
                    a = ffma2(w.y, zp5[2 * t + 1], a);
                }
                #pragma unroll
                for (int t = 0; t < 5; t++) {
                    ulonglong2 w = *(const ulonglong2*)(wr + othoff + 4 * t);
                    a = ffma2(w.x, pz5[2 * t], a);
                    a = ffma2(w.y, pz5[2 * t + 1], a);
                }
                fv[q] = fold2(a);
            }
            float4 v = make_float4(fv[0], fv[1], fv[2], fv[3]);
            if (valid) *(float4*)(outr + col) = v;
            if (hasnext) {
                float4 xv = *(const float4*)(xn + col);
                ull d01 = pack2(v.x - xv.x, v.y - xv.y);
                ull d23 = pack2(v.z - xv.z, v.w - xv.w);
                p0acc = ffma2(d01, d01, p0acc);
                p0acc = ffma2(d23, d23, p0acc);
            }
        }
        // tail/head float2: even -> (48,49); odd -> (50,51)
        {
            const int col = half ? 50 : 48;
            float fv[2];
            #pragma unroll
            for (int q = 0; q < 2; q++) {
                int mm = col + q;
                ull a = pack2(s[OFF_B2 + mm], 0.0f);
                const float* wr = s + OFF_W2 + (size_t)mm * 40;
                #pragma unroll
                for (int t = 0; t < 5; t++) {
                    ulonglong2 w = *(const ulonglong2*)(wr + ownoff + 4 * t);
                    a = ffma2(w.x, zp5[2 * t], a);
                    a = ffma2(w.y, zp5[2 * t + 1], a);
                }
                #pragma unroll
                for (int t = 0; t < 5; t++) {
                    ulonglong2 w = *(const ulonglong2*)(wr + othoff + 4 * t);
                    a = ffma2(w.x, pz5[2 * t], a);
                    a = ffma2(w.y, pz5[2 * t + 1], a);
                }
                fv[q] = fold2(a);
            }
            float2 v = make_float2(fv[0], fv[1]);
            if (valid) *(float2*)(outr + col) = v;
            if (hasnext) {
                float2 xv = *(const float2*)(xn + col);
                ull d = pack2(v.x - xv.x, v.y - xv.y);
                p0acc = ffma2(d, d, p0acc);
            }
        }
        p0 = fold2(p0acc);
    }

    // ---- block reduction of part0, one double atomic per CTA ----
    #pragma unroll
    for (int o = 16; o > 0; o >>= 1) p0 += __shfl_down_sync(0xffffffffu, p0, o);
    __shared__ float red[TPB / 32];
    const int wid = tid >> 5, lane = tid & 31;
    if (lane == 0) red[wid] = p0;
    __syncthreads();
    if (tid == 0) {
        float acc = 0.0f;
        #pragma unroll
        for (int i = 0; i < TPB / 32; i++) acc += red[i];
        atomicAdd(&g_p0, (double)acc);
    }
}

// ---------------- h statistics (float inner accumulation) ----------------
#define HS_ROWS 512
__global__ void h_stats(const float* __restrict__ h) {
    const int col = threadIdx.x;  // 128 threads, cols 0..99 active
    const long long r0 = (long long)blockIdx.x * HS_ROWS;
    long long r1 = r0 + HS_ROWS; if (r1 > N_ROWS) r1 = N_ROWS;

    float csum = 0.0f, sq = 0.0f, dif = 0.0f;
    if (col < 100 && r0 < N_ROWS) {
        float prev = h[r0 * 100 + col];
        csum = prev; sq = prev * prev;
        #pragma unroll 8
        for (long long r = r0 + 1; r < r1; ++r) {
            float v = h[r * 100 + col];
            csum += v;
            sq   = fmaf(v, v, sq);
            dif  += fabsf(v - prev);
            prev = v;
        }
        if (r1 < N_ROWS) {
            float v = h[r1 * 100 + col];
            dif += fabsf(v - prev);
        }
        atomicAdd(&g_mu[col], (double)csum);
    }

    __shared__ float ssq[128], sdf[128];
    ssq[threadIdx.x] = sq; sdf[threadIdx.x] = dif;
    __syncthreads();
    for (int off = 64; off > 0; off >>= 1) {
        if (threadIdx.x < off) {
            ssq[threadIdx.x] += ssq[threadIdx.x + off];
            sdf[threadIdx.x] += sdf[threadIdx.x + off];
        }
        __syncthreads();
    }
    if (threadIdx.x == 0) {
        atomicAdd(&g_sq,   (double)ssq[0]);
        atomicAdd(&g_diff, (double)sdf[0]);
    }
}

// ---------------- finalize scalars (parallel) ----------------
__global__ void finalize(float* __restrict__ out) {
    __shared__ double sm[128];
    const int t = threadIdx.x;
    sm[t] = (t < 100) ? fabs(g_mu[t] / (double)N_ROWS) : 0.0;
    __syncthreads();
    for (int off = 64; off > 0; off >>= 1) {
        if (t < off) sm[t] += sm[t + off];
        __syncthreads();
    }
    if (t == 0) {
        out[OUT_SCALAR + 0] = (float)(sqrt(g_p0) / (double)(N_ROWS - 1));
        out[OUT_SCALAR + 1] = (float)(sm[0] / 100.0);
        out[OUT_SCALAR + 2] = (float)fabs(g_sq / (double)N_ROWS / 100.0 - 1.0);
        out[OUT_SCALAR + 3] = (float)(g_diff / (double)(N_ROWS - 1) / 100.0);
    }
}

// ---------------- launch ----------------
extern "C" void kernel_launch(void* const* d_in, const int* in_sizes, int n_in,
                              void* d_out, int out_size) {
    const float* x   = (const float*)d_in[0];
    const float* h   = (const float*)d_in[1];
    const float* w1  = (const float*)d_in[2];
    const float* b1  = (const float*)d_in[3];
    const float* w12 = (const float*)d_in[4];
    const float* b12 = (const float*)d_in[5];
    const float* w13 = (const float*)d_in[6];
    const float* b13 = (const float*)d_in[7];
    const float* w14 = (const float*)d_in[8];
    const float* b14 = (const float*)d_in[9];
    const float* w15 = (const float*)d_in[10];
    const float* b15 = (const float*)d_in[11];
    const float* w2  = (const float*)d_in[12];
    const float* b2  = (const float*)d_in[13];
    float* out = (float*)d_out;

    (void)in_sizes; (void)n_in; (void)out_size;

    cudaFuncSetAttribute(fused_mlp, cudaFuncAttributeMaxDynamicSharedMemorySize, SH_BYTES);

    const long long total_threads = 2LL * N_ROWS;
    const int blocks = (int)((total_threads + TPB - 1) / TPB);

    init_kernel<<<1, 128>>>();
    fused_mlp<<<blocks, TPB, SH_BYTES>>>(
        x, h, w1, b1, w12, b12, w13, b13, w14, b14, w15, b15, w2, b2, out);
    h_stats<<<(N_ROWS + HS_ROWS - 1) / HS_ROWS, 128>>>(h);
    finalize<<<1, 32 * 4>>>(out);
}

// round 6
// speedup vs baseline: 1.7689x; 1.0242x over previous
#include <cuda_runtime.h>
#include <math.h>

#define N_ROWS 500000
#define TPB 512
#define ROWS_PER_CTA 512   // 2 threads per row-pair, 2 rows per thread

typedef unsigned long long ull;

// ---------------- f32x2 packed helpers (Blackwell sm_103a) ----------------
__device__ __forceinline__ ull ffma2(ull a, ull b, ull c) {
    ull d;
    asm("fma.rn.f32x2 %0, %1, %2, %3;" : "=l"(d) : "l"(a), "l"(b), "l"(c));
    return d;
}
__device__ __forceinline__ ull pack2(float lo, float hi) {
    float2 t = make_float2(lo, hi);
    return *reinterpret_cast<ull*>(&t);
}
__device__ __forceinline__ ull bcast2(float v) { return pack2(v, v); }
__device__ __forceinline__ float lo2(ull v) { return reinterpret_cast<float2*>(&v)->x; }
__device__ __forceinline__ float hi2(ull v) { return reinterpret_cast<float2*>(&v)->y; }
__device__ __forceinline__ float fold2(ull v) {
    float2 t = *reinterpret_cast<float2*>(&v);
    return t.x + t.y;
}
__device__ __forceinline__ ull relu2(ull v) {
    float2 t = *reinterpret_cast<float2*>(&v);
    t.x = fmaxf(t.x, 0.0f); t.y = fmaxf(t.y, 0.0f);
    return *reinterpret_cast<ull*>(&t);
}
__device__ __forceinline__ ull shflx1(ull v) {   // exchange with pair mate
    return __shfl_xor_sync(0xffffffffu, v, 1);
}
__device__ __forceinline__ float f4elem(const float4& v, int i) {
    return (i == 0) ? v.x : (i == 1) ? v.y : (i == 2) ? v.z : v.w;
}

// -------- shared-memory layout (floats; every LDS.128 lands 16B-aligned) --
#define OFF_W1T  0          // 200 x 104 (cols 0..49 = out 0..49; 52..101 = out 50..99)
#define OFF_B1   20800
#define OFF_W12T 20900      // 100 x 56
#define OFF_B12  26500
#define OFF_W13  26552      // 30 x 156 (cols 0..55 z2-padded, 56..155 h)
#define OFF_B13  31232
#define OFF_W14  31264      // 20 x 32 (z3 c -> c<15?c:c+1)
#define OFF_B14  31904
#define OFF_W15  31924      // 40 x 124 (z4 c -> c<10?c:c+2 ; 24..123 h)
#define OFF_B15  36884
#define OFF_W2   36924      // 100 x 40
#define OFF_B2   40924
#define SH_FLOATS 41024
#define SH_BYTES (SH_FLOATS * 4)

#define OUT_SCALAR ((size_t)N_ROWS * 100)

// ---------------- global accumulators ----------------
__device__ double g_p0;
__device__ double g_sq;
__device__ double g_diff;
__device__ double g_mu[100];

__global__ void init_kernel() {
    int t = threadIdx.x;
    if (t == 0) { g_p0 = 0.0; g_sq = 0.0; g_diff = 0.0; }
    if (t < 100) g_mu[t] = 0.0;
}

// --- fused MLP: 2 rows per thread, half-split output pairs (R=2 blocking) --
__global__ void __launch_bounds__(TPB, 1) fused_mlp(
    const float* __restrict__ x, const float* __restrict__ h,
    const float* __restrict__ w1,  const float* __restrict__ b1,
    const float* __restrict__ w12, const float* __restrict__ b12,
    const float* __restrict__ w13, const float* __restrict__ b13,
    const float* __restrict__ w14, const float* __restrict__ b14,
    const float* __restrict__ w15, const float* __restrict__ b15,
    const float* __restrict__ w2,  const float* __restrict__ b2,
    float* __restrict__ out)
{
    extern __shared__ float s[];
    const int tid = threadIdx.x;

    // ---- phase A: zero padded regions ----
    for (int i = tid; i < 20800; i += TPB) s[OFF_W1T + i] = 0.0f;
    for (int i = tid; i < 5600;  i += TPB) s[OFF_W12T + i] = 0.0f;
    for (int i = tid; i < 4680;  i += TPB) s[OFF_W13 + i] = 0.0f;
    for (int i = tid; i < 640;   i += TPB) s[OFF_W14 + i] = 0.0f;
    for (int i = tid; i < 4960;  i += TPB) s[OFF_W15 + i] = 0.0f;
    __syncthreads();

    // ---- phase B: fill ----
    for (int i = tid; i < 20000; i += TPB) {
        int k = i / 100, m = i % 100;
        int col = (m < 50) ? m : (m + 2);
        s[OFF_W1T + k * 104 + col] = w1[m * 200 + k];
    }
    for (int i = tid; i < 100;   i += TPB) s[OFF_B1 + i] = b1[i];
    for (int i = tid; i < 5000;  i += TPB) {
        int n = i / 100, k = i % 100;
        s[OFF_W12T + k * 56 + n] = w12[i];
    }
    for (int i = tid; i < 50;    i += TPB) s[OFF_B12 + i] = b12[i];
    for (int i = tid; i < 4500;  i += TPB) {
        int r_ = i / 150, c = i % 150;
        s[OFF_W13 + r_ * 156 + (c < 50 ? c : c + 6)] = w13[i];
    }
    for (int i = tid; i < 30;    i += TPB) s[OFF_B13 + i] = b13[i];
    for (int i = tid; i < 600;   i += TPB) {
        int r_ = i / 30, c = i % 30;
        s[OFF_W14 + r_ * 32 + (c < 15 ? c : c + 1)] = w14[i];
    }
    for (int i = tid; i < 20;    i += TPB) s[OFF_B14 + i] = b14[i];
    for (int i = tid; i < 4800;  i += TPB) {
        int r_ = i / 120, c = i % 120;
        int col = (c < 10) ? c : (c < 20) ? (c + 2) : (c + 4);
        s[OFF_W15 + r_ * 124 + col] = w15[i];
    }
    for (int i = tid; i < 40;    i += TPB) s[OFF_B15 + i] = b15[i];
    for (int i = tid; i < 4000;  i += TPB) s[OFF_W2 + i] = w2[i];
    for (int i = tid; i < 100;   i += TPB) s[OFF_B2 + i] = b2[i];
    __syncthreads();

    const int half = tid & 1;
    const int pr = tid >> 1;                   // pair index within CTA
    int rA = blockIdx.x * ROWS_PER_CTA + 2 * pr;
    const bool valid = (rA + 1 < N_ROWS);
    if (!valid) rA = N_ROWS - 2;               // clamp; pair stays converged
    const int rB = rA + 1;

    const float* xA = x + (size_t)rA * 100;
    const float* xB = x + (size_t)rB * 100;
    const float* hA = h + (size_t)rA * 100;
    const float* hB = h + (size_t)rB * 100;

    // ====== layers 1+2 fused; 3 output passes of {16,16,18} cols =========
    ull z2p[14][2];
    #pragma unroll
    for (int t = 0; t < 14; t++) {
        int c = half * 28 + 2 * t;
        float b0  = (c     < 50) ? s[OFF_B12 + c]     : 0.0f;
        float b1v = (c + 1 < 50) ? s[OFF_B12 + c + 1] : 0.0f;
        ull b = pack2(b0, b1v);
        z2p[t][0] = b; z2p[t][1] = b;
    }

    #pragma unroll 1
    for (int pass = 0; pass < 3; ++pass) {
        const int cs = pass * 16;              // col start within half region
        const int nu = (pass == 2) ? 9 : 8;    // ull count this pass
        const int woff = half * 52 + cs;

        ull accA[9], accB[9];
        #pragma unroll
        for (int j = 0; j < 9; j++) {
            if (j < nu) {
                ull b = pack2(s[OFF_B1 + half * 50 + cs + 2 * j],
                              s[OFF_B1 + half * 50 + cs + 2 * j + 1]);
                accA[j] = b; accB[j] = b;
            } else { accA[j] = 0ull; accB[j] = 0ull; }
        }

        // fused x+h streaming with depth-1 prefetch
        float4 nxA = *(const float4*)(xA), nxB = *(const float4*)(xB);
        float4 nhA = *(const float4*)(hA), nhB = *(const float4*)(hB);
        #pragma unroll 1
        for (int k = 0; k < 100; k += 4) {
            float4 cxA = nxA, cxB = nxB, chA = nhA, chB = nhB;
            int knx = (k + 4 < 100) ? (k + 4) : 0;
            nxA = *(const float4*)(xA + knx); nxB = *(const float4*)(xB + knx);
            nhA = *(const float4*)(hA + knx); nhB = *(const float4*)(hB + knx);

            #pragma unroll
            for (int i = 0; i < 4; i++) {
                // x contribution: W1T row (k+i)
                {
                    ull vA = bcast2(f4elem(cxA, i)), vB = bcast2(f4elem(cxB, i));
                    const float* wr = s + OFF_W1T + (size_t)(k + i) * 104 + woff;
                    #pragma unroll
                    for (int q = 0; q < 4; q++) {
                        ulonglong2 w = *(const ulonglong2*)(wr + 4 * q);
                        accA[2 * q]     = ffma2(w.x, vA, accA[2 * q]);
                        accA[2 * q + 1] = ffma2(w.y, vA, accA[2 * q + 1]);
                        accB[2 * q]     = ffma2(w.x, vB, accB[2 * q]);
                        accB[2 * q + 1] = ffma2(w.y, vB, accB[2 * q + 1]);
                    }
                    if (nu == 9) {
                        ull wl = *(const ull*)(wr + 16);
                        accA[8] = ffma2(wl, vA, accA[8]);
                        accB[8] = ffma2(wl, vB, accB[8]);
                    }
                }
                // h contribution: W1T row (100+k+i)
                {
                    ull vA = bcast2(f4elem(chA, i)), vB = bcast2(f4elem(chB, i));
                    const float* wr = s + OFF_W1T + (size_t)(100 + k + i) * 104 + woff;
                    #pragma unroll
                    for (int q = 0; q < 4; q++) {
                        ulonglong2 w = *(const ulonglong2*)(wr + 4 * q);
                        accA[2 * q]     = ffma2(w.x, vA, accA[2 * q]);
                        accA[2 * q + 1] = ffma2(w.y, vA, accA[2 * q + 1]);
                        accB[2 * q]     = ffma2(w.x, vB, accB[2 * q]);
                        accB[2 * q + 1] = ffma2(w.y, vB, accB[2 * q + 1]);
                    }
                    if (nu == 9) {
                        ull wl = *(const ull*)(wr + 16);
                        accA[8] = ffma2(wl, vA, accA[8]);
                        accB[8] = ffma2(wl, vB, accB[8]);
                    }
                }
            }
        }

        // relu + fused L2 accumulation for this pass's outputs
        #pragma unroll 1
        for (int j = 0; j < nu; j++) {
            ull oA = relu2(accA[j]), oB = relu2(accB[j]);
            ull mA = shflx1(oA),     mB = shflx1(oB);
            float sa[4] = { lo2(oA), hi2(oA), lo2(mA), hi2(mA) };
            float sb[4] = { lo2(oB), hi2(oB), lo2(mB), hi2(mB) };
            const int kown = half * 50 + cs + 2 * j;
            const int koth = (1 - half) * 50 + cs + 2 * j;
            int ks[4] = { kown, kown + 1, koth, koth + 1 };
            #pragma unroll
            for (int slot = 0; slot < 4; slot++) {
                ull zA = bcast2(sa[slot]), zB = bcast2(sb[slot]);
                const float* wr = s + OFF_W12T + (size_t)ks[slot] * 56 + half * 28;
                #pragma unroll
                for (int q = 0; q < 7; q++) {
                    ulonglong2 w = *(const ulonglong2*)(wr + 4 * q);
                    z2p[2 * q][0]     = ffma2(w.x, zA, z2p[2 * q][0]);
                    z2p[2 * q + 1][0] = ffma2(w.y, zA, z2p[2 * q + 1][0]);
                    z2p[2 * q][1]     = ffma2(w.x, zB, z2p[2 * q][1]);
                    z2p[2 * q + 1][1] = ffma2(w.y, zB, z2p[2 * q + 1][1]);
                }
            }
        }
    }
    #pragma unroll
    for (int t = 0; t < 14; t++) { z2p[t][0] = relu2(z2p[t][0]); z2p[t][1] = relu2(z2p[t][1]); }

    // ====== layer 3: 15 outputs/thread, 2 passes (8,7), both rows =========
    float z3A[16], z3B[16];
    #pragma unroll 1
    for (int p3 = 0; p3 < 2; ++p3) {
        const int m0 = p3 * 8;
        const int cnt = p3 ? 7 : 8;
        ull acc[8][2];
        #pragma unroll
        for (int m = 0; m < 8; m++) {
            ull b = (m < cnt) ? pack2(s[OFF_B13 + half * 15 + m0 + m], 0.0f) : 0ull;
            acc[m][0] = b; acc[m][1] = b;
        }
        // z2 part
        #pragma unroll 1
        for (int q = 0; q < 7; q++) {
            ull zA0 = z2p[2 * q][0], zA1 = z2p[2 * q + 1][0];
            ull zB0 = z2p[2 * q][1], zB1 = z2p[2 * q + 1][1];
            ull mA0 = shflx1(zA0), mA1 = shflx1(zA1);
            ull mB0 = shflx1(zB0), mB1 = shflx1(zB1);
            #pragma unroll
            for (int m = 0; m < 8; m++) {
                if (m >= cnt) break;
                const float* base = s + OFF_W13 + (size_t)(half * 15 + m0 + m) * 156;
                ulonglong2 wo = *(const ulonglong2*)(base + half * 28 + 4 * q);
                acc[m][0] = ffma2(wo.x, zA0, acc[m][0]);
                acc[m][0] = ffma2(wo.y, zA1, acc[m][0]);
                acc[m][1] = ffma2(wo.x, zB0, acc[m][1]);
                acc[m][1] = ffma2(wo.y, zB1, acc[m][1]);
                ulonglong2 wm = *(const ulonglong2*)(base + (1 - half) * 28 + 4 * q);
                acc[m][0] = ffma2(wm.x, mA0, acc[m][0]);
                acc[m][0] = ffma2(wm.y, mA1, acc[m][0]);
                acc[m][1] = ffma2(wm.x, mB0, acc[m][1]);
                acc[m][1] = ffma2(wm.y, mB1, acc[m][1]);
            }
        }
        // h part (prefetched)
        {
            float4 nA = *(const float4*)(hA), nB = *(const float4*)(hB);
            #pragma unroll 1
            for (int k = 0; k < 100; k += 4) {
                float4 cA = nA, cB = nB;
                int knx = (k + 4 < 100) ? (k + 4) : 0;
                nA = *(const float4*)(hA + knx); nB = *(const float4*)(hB + knx);
                ulonglong2 uA = *reinterpret_cast<ulonglong2*>(&cA);
                ulonglong2 uB = *reinterpret_cast<ulonglong2*>(&cB);
                #pragma unroll
                for (int m = 0; m < 8; m++) {
                    if (m >= cnt) break;
                    const float* base = s + OFF_W13 + (size_t)(half * 15 + m0 + m) * 156;
                    ulonglong2 w = *(const ulonglong2*)(base + 56 + k);
                    acc[m][0] = ffma2(w.x, uA.x, acc[m][0]);
                    acc[m][0] = ffma2(w.y, uA.y, acc[m][0]);
                    acc[m][1] = ffma2(w.x, uB.x, acc[m][1]);
                    acc[m][1] = ffma2(w.y, uB.y, acc[m][1]);
                }
            }
        }
        #pragma unroll
        for (int m = 0; m < 8; m++) {
            if (m >= cnt) break;
            z3A[m0 + m] = fmaxf(fold2(acc[m][0]), 0.0f);
            z3B[m0 + m] = fmaxf(fold2(acc[m][1]), 0.0f);
        }
    }
    z3A[15] = 0.0f; z3B[15] = 0.0f;

    // ====== layer 4: 10 outputs/thread ====================================
    float z4A[10], z4B[10];
    {
        ull zp3A[8], zp3B[8];
        #pragma unroll
        for (int t = 0; t < 8; t++) {
            zp3A[t] = pack2(z3A[2 * t], z3A[2 * t + 1]);
            zp3B[t] = pack2(z3B[2 * t], z3B[2 * t + 1]);
        }
        ull acc[10][2];
        #pragma unroll
        for (int m = 0; m < 10; m++) {
            ull b = pack2(s[OFF_B14 + half * 10 + m], 0.0f);
            acc[m][0] = b; acc[m][1] = b;
        }
        #pragma unroll 1
        for (int q = 0; q < 4; q++) {
            ull zA0 = zp3A[2 * q], zA1 = zp3A[2 * q + 1];
            ull zB0 = zp3B[2 * q], zB1 = zp3B[2 * q + 1];
            ull mA0 = shflx1(zA0), mA1 = shflx1(zA1);
            ull mB0 = shflx1(zB0), mB1 = shflx1(zB1);
            #pragma unroll
            for (int m = 0; m < 10; m++) {
                const float* base = s + OFF_W14 + (size_t)(half * 10 + m) * 32;
                ulonglong2 wo = *(const ulonglong2*)(base + half * 16 + 4 * q);
                acc[m][0] = ffma2(wo.x, zA0, acc[m][0]);
                acc[m][0] = ffma2(wo.y, zA1, acc[m][0]);
                acc[m][1] = ffma2(wo.x, zB0, acc[m][1]);
                acc[m][1] = ffma2(wo.y, zB1, acc[m][1]);
                ulonglong2 wm = *(const ulonglong2*)(base + (1 - half) * 16 + 4 * q);
                acc[m][0] = ffma2(wm.x, mA0, acc[m][0]);
                acc[m][0] = ffma2(wm.y, mA1, acc[m][0]);
                acc[m][1] = ffma2(wm.x, mB0, acc[m][1]);
                acc[m][1] = ffma2(wm.y, mB1, acc[m][1]);
            }
        }
        #pragma unroll
        for (int m = 0; m < 10; m++) {
            z4A[m] = fmaxf(fold2(acc[m][0]), 0.0f);
            z4B[m] = fmaxf(fold2(acc[m][1]), 0.0f);
        }
    }

    // ====== layer 5: 20 outputs/thread, single pass =======================
    float z5A[20], z5B[20];
    {
        ull zp4A[6], zp4B[6];
        #pragma unroll
        for (int t = 0; t < 5; t++) {
            zp4A[t] = pack2(z4A[2 * t], z4A[2 * t + 1]);
            zp4B[t] = pack2(z4B[2 * t], z4B[2 * t + 1]);
        }
        zp4A[5] = 0ull; zp4B[5] = 0ull;

        ull acc[20][2];
        #pragma unroll
        for (int m = 0; m < 20; m++) {
            ull b = pack2(s[OFF_B15 + half * 20 + m], 0.0f);
            acc[m][0] = b; acc[m][1] = b;
        }
        #pragma unroll 1
        for (int q = 0; q < 3; q++) {
            ull zA0 = zp4A[2 * q], zA1 = zp4A[2 * q + 1];
            ull zB0 = zp4B[2 * q], zB1 = zp4B[2 * q + 1];
            ull mA0 = shflx1(zA0), mA1 = shflx1(zA1);
            ull mB0 = shflx1(zB0), mB1 = shflx1(zB1);
            #pragma unroll
            for (int m = 0; m < 20; m++) {
                const float* base = s + OFF_W15 + (size_t)(half * 20 + m) * 124;
                ulonglong2 wo = *(const ulonglong2*)(base + half * 12 + 4 * q);
                acc[m][0] = ffma2(wo.x, zA0, acc[m][0]);
                acc[m][0] = ffma2(wo.y, zA1, acc[m][0]);
                acc[m][1] = ffma2(wo.x, zB0, acc[m][1]);
                acc[m][1] = ffma2(wo.y, zB1, acc[m][1]);
                ulonglong2 wm = *(const ulonglong2*)(base + (1 - half) * 12 + 4 * q);
                acc[m][0] = ffma2(wm.x, mA0, acc[m][0]);
                acc[m][0] = ffma2(wm.y, mA1, acc[m][0]);
                acc[m][1] = ffma2(wm.x, mB0, acc[m][1]);
                acc[m][1] = ffma2(wm.y, mB1, acc[m][1]);
            }
        }
        // h part (prefetched)
        {
            float4 nA = *(const float4*)(hA), nB = *(const float4*)(hB);
            #pragma unroll 1
            for (int k = 0; k < 100; k += 4) {
                float4 cA = nA, cB = nB;
                int knx = (k + 4 < 100) ? (k + 4) : 0;
                nA = *(const float4*)(hA + knx); nB = *(const float4*)(hB + knx);
                ulonglong2 uA = *reinterpret_cast<ulonglong2*>(&cA);
                ulonglong2 uB = *reinterpret_cast<ulonglong2*>(&cB);
                #pragma unroll
                for (int m = 0; m < 20; m++) {
                    const float* base = s + OFF_W15 + (size_t)(half * 20 + m) * 124;
                    ulonglong2 w = *(const ulonglong2*)(base + 24 + k);
                    acc[m][0] = ffma2(w.x, uA.x, acc[m][0]);
                    acc[m][0] = ffma2(w.y, uA.y, acc[m][0]);
                    acc[m][1] = ffma2(w.x, uB.x, acc[m][1]);
                    acc[m][1] = ffma2(w.y, uB.y, acc[m][1]);
                }
            }
        }
        #pragma unroll
        for (int m = 0; m < 20; m++) {
            z5A[m] = fmaxf(fold2(acc[m][0]), 0.0f);
            z5B[m] = fmaxf(fold2(acc[m][1]), 0.0f);
        }
    }

    // ====== output layer + fused part0, both rows =========================
    float p0 = 0.0f;
    {
        ull zp5A[10], zp5B[10], pz5A[10], pz5B[10];
        #pragma unroll
        for (int t = 0; t < 10; t++) {
            zp5A[t] = pack2(z5A[2 * t], z5A[2 * t + 1]);
            zp5B[t] = pack2(z5B[2 * t], z5B[2 * t + 1]);
            pz5A[t] = shflx1(zp5A[t]);
            pz5B[t] = shflx1(zp5B[t]);
        }
        const int ownoff = half * 20, othoff = (1 - half) * 20;

        float* outA = out + (size_t)rA * 100;
        float* outB = out + (size_t)rB * 100;
        const float* xnA = xB;                         // x[rA+1]
        const float* xnB = x + (size_t)(rB + 1) * 100;
        const bool hnA = valid;
        const bool hnB = valid && (rB + 1 < N_ROWS);
        ull p0acc = 0ull;

        #pragma unroll 1
        for (int c = 0; c < 12; c++) {
            const int col = half * 52 + 4 * c;
            float fvA[4], fvB[4];
            #pragma unroll
            for (int qq = 0; qq < 4; qq++) {
                int mm = col + qq;
                ull aA = pack2(s[OFF_B2 + mm], 0.0f);
                ull aB = aA;
                const float* wr = s + OFF_W2 + (size_t)mm * 40;
                #pragma unroll
                for (int t = 0; t < 5; t++) {
                    ulonglong2 w = *(const ulonglong2*)(wr + ownoff + 4 * t);
                    aA = ffma2(w.x, zp5A[2 * t], aA);
                    aA = ffma2(w.y, zp5A[2 * t + 1], aA);
                    aB = ffma2(w.x, zp5B[2 * t], aB);
                    aB = ffma2(w.y, zp5B[2 * t + 1], aB);
                }
                #pragma unroll
                for (int t = 0; t < 5; t++) {
                    ulonglong2 w = *(const ulonglong2*)(wr + othoff + 4 * t);
                    aA = ffma2(w.x, pz5A[2 * t], aA);
                    aA = ffma2(w.y, pz5A[2 * t + 1], aA);
                    aB = ffma2(w.x, pz5B[2 * t], aB);
                    aB = ffma2(w.y, pz5B[2 * t + 1], aB);
                }
                fvA[qq] = fold2(aA); fvB[qq] = fold2(aB);
            }
            float4 vA = make_float4(fvA[0], fvA[1], fvA[2], fvA[3]);
            float4 vB = make_float4(fvB[0], fvB[1], fvB[2], fvB[3]);
            if (valid) { *(float4*)(outA + col) = vA; *(float4*)(outB + col) = vB; }
            if (hnA) {
                float4 xv = *(const float4*)(xnA + col);
                ull d01 = pack2(vA.x - xv.x, vA.y - xv.y);
                ull d23 = pack2(vA.z - xv.z, vA.w - xv.w);
                p0acc = ffma2(d01, d01, p0acc);
                p0acc = ffma2(d23, d23, p0acc);
            }
            if (hnB) {
                float4 xv = *(const float4*)(xnB + col);
                ull d01 = pack2(vB.x - xv.x, vB.y - xv.y);
                ull d23 = pack2(vB.z - xv.z, vB.w - xv.w);
                p0acc = ffma2(d01, d01, p0acc);
                p0acc = ffma2(d23, d23, p0acc);
            }
        }
        // tail float2: even half -> cols 48,49 ; odd half -> cols 50,51
        {
            const int col = half ? 50 : 48;
            float fvA[2], fvB[2];
            #pragma unroll
            for (int qq = 0; qq < 2; qq++) {
                int mm = col + qq;
                ull aA = pack2(s[OFF_B2 + mm], 0.0f);
                ull aB = aA;
                const float* wr = s + OFF_W2 + (size_t)mm * 40;
                #pragma unroll
                for (int t = 0; t < 5; t++) {
                    ulonglong2 w = *(const ulonglong2*)(wr + ownoff + 4 * t);
                    aA = ffma2(w.x, zp5A[2 * t], aA);
                    aA = ffma2(w.y, zp5A[2 * t + 1], aA);
                    aB = ffma2(w.x, zp5B[2 * t], aB);
                    aB = ffma2(w.y, zp5B[2 * t + 1], aB);
                }
                #pragma unroll
                for (int t = 0; t < 5; t++) {
                    ulonglong2 w = *(const ulonglong2*)(wr + othoff + 4 * t);
                    aA = ffma2(w.x, pz5A[2 * t], aA);
                    aA = ffma2(w.y, pz5A[2 * t + 1], aA);
                    aB = ffma2(w.x, pz5B[2 * t], aB);
                    aB = ffma2(w.y, pz5B[2 * t + 1], aB);
                }
                fvA[qq] = fold2(aA); fvB[qq] = fold2(aB);
            }
            float2 vA = make_float2(fvA[0], fvA[1]);
            float2 vB = make_float2(fvB[0], fvB[1]);
            if (valid) { *(float2*)(outA + col) = vA; *(float2*)(outB + col) = vB; }
            if (hnA) {
                float2 xv = *(const float2*)(xnA + col);
                ull d = pack2(vA.x - xv.x, vA.y - xv.y);
                p0acc = ffma2(d, d, p0acc);
            }
            if (hnB) {
                float2 xv = *(const float2*)(xnB + col);
                ull d = pack2(vB.x - xv.x, vB.y - xv.y);
                p0acc = ffma2(d, d, p0acc);
            }
        }
        p0 = fold2(p0acc);
    }

    // ---- block reduction of part0, one double atomic per CTA ----
    #pragma unroll
    for (int o = 16; o > 0; o >>= 1) p0 += __shfl_down_sync(0xffffffffu, p0, o);
    __shared__ float red[TPB / 32];
    const int wid = tid >> 5, lane = tid & 31;
    if (lane == 0) red[wid] = p0;
    __syncthreads();
    if (tid == 0) {
        float acc = 0.0f;
        #pragma unroll
        for (int i = 0; i < TPB / 32; i++) acc += red[i];
        atomicAdd(&g_p0, (double)acc);
    }
}

// ---------------- h statistics (float inner accumulation) ----------------
#define HS_ROWS 512
__global__ void h_stats(const float* __restrict__ h) {
    const int col = threadIdx.x;  // 128 threads, cols 0..99 active
    const long long r0 = (long long)blockIdx.x * HS_ROWS;
    long long r1 = r0 + HS_ROWS; if (r1 > N_ROWS) r1 = N_ROWS;

    float csum = 0.0f, sq = 0.0f, dif = 0.0f;
    if (col < 100 && r0 < N_ROWS) {
        float prev = h[r0 * 100 + col];
        csum = prev; sq = prev * prev;
        #pragma unroll 8
        for (long long r = r0 + 1; r < r1; ++r) {
            float v = h[r * 100 + col];
            csum += v;
            sq   = fmaf(v, v, sq);
            dif  += fabsf(v - prev);
            prev = v;
        }
        if (r1 < N_ROWS) {
            float v = h[r1 * 100 + col];
            dif += fabsf(v - prev);
        }
        atomicAdd(&g_mu[col], (double)csum);
    }

    __shared__ float ssq[128], sdf[128];
    ssq[threadIdx.x] = sq; sdf[threadIdx.x] = dif;
    __syncthreads();
    for (int off = 64; off > 0; off >>= 1) {
        if (threadIdx.x < off) {
            ssq[threadIdx.x] += ssq[threadIdx.x + off];
            sdf[threadIdx.x] += sdf[threadIdx.x + off];
        }
        __syncthreads();
    }
    if (threadIdx.x == 0) {
        atomicAdd(&g_sq,   (double)ssq[0]);
        atomicAdd(&g_diff, (double)sdf[0]);
    }
}

// ---------------- finalize scalars (parallel) ----------------
__global__ void finalize(float* __restrict__ out) {
    __shared__ double sm[128];
    const int t = threadIdx.x;
    sm[t] = (t < 100) ? fabs(g_mu[t] / (double)N_ROWS) : 0.0;
    __syncthreads();
    for (int off = 64; off > 0; off >>= 1) {
        if (t < off) sm[t] += sm[t + off];
        __syncthreads();
    }
    if (t == 0) {
        out[OUT_SCALAR + 0] = (float)(sqrt(g_p0) / (double)(N_ROWS - 1));
        out[OUT_SCALAR + 1] = (float)(sm[0] / 100.0);
        out[OUT_SCALAR + 2] = (float)fabs(g_sq / (double)N_ROWS / 100.0 - 1.0);
        out[OUT_SCALAR + 3] = (float)(g_diff / (double)(N_ROWS - 1) / 100.0);
    }
}

// ---------------- launch ----------------
extern "C" void kernel_launch(void* const* d_in, const int* in_sizes, int n_in,
                              void* d_out, int out_size) {
    const float* x   = (const float*)d_in[0];
    const float* h   = (const float*)d_in[1];
    const float* w1  = (const float*)d_in[2];
    const float* b1  = (const float*)d_in[3];
    const float* w12 = (const float*)d_in[4];
    const float* b12 = (const float*)d_in[5];
    const float* w13 = (const float*)d_in[6];
    const float* b13 = (const float*)d_in[7];
    const float* w14 = (const float*)d_in[8];
    const float* b14 = (const float*)d_in[9];
    const float* w15 = (const float*)d_in[10];
    const float* b15 = (const float*)d_in[11];
    const float* w2  = (const float*)d_in[12];
    const float* b2  = (const float*)d_in[13];
    float* out = (float*)d_out;

    (void)in_sizes; (void)n_in; (void)out_size;

    cudaFuncSetAttribute(fused_mlp, cudaFuncAttributeMaxDynamicSharedMemorySize, SH_BYTES);

    const int blocks = (N_ROWS + ROWS_PER_CTA - 1) / ROWS_PER_CTA;

    init_kernel<<<1, 128>>>();
    fused_mlp<<<blocks, TPB, SH_BYTES>>>(
        x, h, w1, b1, w12, b12, w13, b13, w14, b14, w15, b15, w2, b2, out);
    h_stats<<<(N_ROWS + HS_ROWS - 1) / HS_ROWS, 128>>>(h);
    finalize<<<1, 32 * 4>>>(out);
}